// round 4
// baseline (speedup 1.0000x reference)
#include <cuda_runtime.h>
#include <cstdint>

#define N_OBS   50000
#define N_TOTAL 100000
#define F       64
#define P       16
#define H       256
#define G3      768        // 3*H
#define XK      1024       // F*P
#define TWO_LOG_LIK_C 1.8378770664093453f

// ---------------- scratch (static __device__ — no allocations) ----------------
__device__ float g_X1 [(size_t)N_OBS * XK];
__device__ float g_X2 [(size_t)N_OBS * XK];
__device__ float g_GI1[(size_t)N_OBS * G3];
__device__ float g_GH1[(size_t)N_OBS * G3];
__device__ float g_GI2[(size_t)N_OBS * G3];
__device__ float g_GH2[(size_t)N_OBS * G3];

__device__ __forceinline__ float sigmoidf_(float x) { return 1.0f / (1.0f + expf(-x)); }

// ---------------- Kernel 1: losses + GCN (factored) + prep features ----------------
__global__ void __launch_bounds__(256) prep_kernel(
    const float* __restrict__ p_obs, const float* __restrict__ X_obs,
    const float* __restrict__ M_obs, const float* __restrict__ adj,
    const float* __restrict__ w_prep, const float* __restrict__ w_prep2,
    const float* __restrict__ bias_prep,
    const float* __restrict__ gcn_w1, const float* __restrict__ gcn_b1,
    const float* __restrict__ gcn_w2, const float* __restrict__ gcn_b2,
    float* __restrict__ losses_out)
{
    __shared__ float adj_s[F * 65];   // padded rows: bank-conflict-free row reads
    __shared__ float xs[F], means[F], lvs[F], errs[F], ms[F];
    __shared__ float axs[F], ss[F], hobs[F];

    const int n = blockIdx.x;
    const int t = threadIdx.x;

    for (int i = t; i < F * F; i += 256)
        adj_s[(i >> 6) * 65 + (i & 63)] = adj[i];

    if (t < F) {
        const int f = t;
        float x    = X_obs[n * F + f];
        float mean = p_obs[n * (2 * F) + f];
        float lv   = p_obs[n * (2 * F) + F + f];
        float m    = M_obs[n * F + f];
        float err  = (x - mean) * expf(-0.5f * lv);
        xs[f] = x; means[f] = mean; lvs[f] = lv; errs[f] = err; ms[f] = m;
        losses_out[n * F + f] = 0.5f * ((err * err + lv + TWO_LOG_LIK_C) * m);
    }
    __syncthreads();

    // ax[f] = sum_g adj[f,g] * X[g]
    if (t < F) {
        const float* ar = adj_s + t * 65;
        float s = 0.0f;
        #pragma unroll 8
        for (int g = 0; g < F; g++) s += ar[g] * xs[g];
        axs[t] = s;
    }
    __syncthreads();

    // s[g] = sum_c w2[c] * relu(ax[g]*w1[c] + b1[c])   (factored GCN layer 2)
    if (t < F) {
        float a = axs[t];
        float acc = 0.0f;
        #pragma unroll
        for (int c = 0; c < 32; c++) {
            float v = fmaf(a, gcn_w1[c], gcn_b1[c]);
            acc = fmaf(gcn_w2[c], fmaxf(v, 0.0f), acc);
        }
        ss[t] = acc;
    }
    __syncthreads();

    // H_obs[f] = sum_g adj[f,g]*s[g] + b2
    if (t < F) {
        const float* ar = adj_s + t * 65;
        float s = gcn_b2[0];
        #pragma unroll 8
        for (int g = 0; g < F; g++) s += ar[g] * ss[g];
        hobs[t] = s;
    }
    __syncthreads();

    // x1: feats (X, mean, logvar, error) @ w_prep[f] + bias, relu, *M
    for (int i = t; i < XK; i += 256) {
        const int f = i >> 4, p = i & 15;
        const float* w = w_prep + f * (4 * P);
        float v = bias_prep[f * P + p];
        v = fmaf(xs[f],    w[p],          v);
        v = fmaf(means[f], w[P + p],      v);
        v = fmaf(lvs[f],   w[2 * P + p],  v);
        v = fmaf(errs[f],  w[3 * P + p],  v);
        g_X1[(size_t)n * XK + i] = fmaxf(v, 0.0f) * ms[f];
    }
    // x2: feats (X, H_obs, mean, logvar, error) @ w_prep2[f]
    for (int i = t; i < XK; i += 256) {
        const int f = i >> 4, p = i & 15;
        const float* w = w_prep2 + f * (5 * P);
        float v = bias_prep[f * P + p];
        v = fmaf(xs[f],    w[p],          v);
        v = fmaf(hobs[f],  w[P + p],      v);
        v = fmaf(means[f], w[2 * P + p],  v);
        v = fmaf(lvs[f],   w[3 * P + p],  v);
        v = fmaf(errs[f],  w[4 * P + p],  v);
        g_X2[(size_t)n * XK + i] = fmaxf(v, 0.0f) * ms[f];
    }
}

// ---------------- Kernel 2: SGEMM  C[M,768] = A[M,K] @ B[768,K]^T + bias ----------------
// 128x128 tile, BK=8, 256 threads, 8x8 per thread. Optional row gather for A.
__global__ void __launch_bounds__(256) sgemm_bias(
    const float* __restrict__ A, int lda, const int* __restrict__ rowidx,
    const float* __restrict__ B, const float* __restrict__ bias,
    float* __restrict__ C, int M, int K)
{
    const int N = G3;
    __shared__ float As[8][132];
    __shared__ float Bs[8][132];

    const int bm = blockIdx.y * 128;
    const int bn = blockIdx.x * 128;
    const int t  = threadIdx.x;
    const int ty = t >> 4;           // 0..15 -> rows ty*8..ty*8+7
    const int tx = t & 15;           // 0..15 -> cols tx*8..tx*8+7
    const int lrow = t >> 1;         // 0..127
    const int lk4  = (t & 1) * 4;    // 0 or 4

    const int  am     = bm + lrow;
    const bool avalid = am < M;
    const int  arow   = avalid ? (rowidx ? rowidx[am] : am) : 0;
    const float* Aptr = A + (size_t)arow * lda + lk4;
    const float* Bptr = B + (size_t)(bn + lrow) * K + lk4;

    float acc[8][8];
    #pragma unroll
    for (int i = 0; i < 8; i++)
        #pragma unroll
        for (int j = 0; j < 8; j++) acc[i][j] = 0.0f;

    for (int kb = 0; kb < K; kb += 8) {
        float4 a4 = avalid ? *(const float4*)(Aptr + kb) : make_float4(0.f, 0.f, 0.f, 0.f);
        float4 b4 = *(const float4*)(Bptr + kb);
        As[lk4 + 0][lrow] = a4.x; As[lk4 + 1][lrow] = a4.y;
        As[lk4 + 2][lrow] = a4.z; As[lk4 + 3][lrow] = a4.w;
        Bs[lk4 + 0][lrow] = b4.x; Bs[lk4 + 1][lrow] = b4.y;
        Bs[lk4 + 2][lrow] = b4.z; Bs[lk4 + 3][lrow] = b4.w;
        __syncthreads();

        #pragma unroll
        for (int kk = 0; kk < 8; kk++) {
            float4 a0 = *(const float4*)&As[kk][ty * 8];
            float4 a1 = *(const float4*)&As[kk][ty * 8 + 4];
            float4 b0 = *(const float4*)&Bs[kk][tx * 8];
            float4 b1 = *(const float4*)&Bs[kk][tx * 8 + 4];
            float av[8] = {a0.x, a0.y, a0.z, a0.w, a1.x, a1.y, a1.z, a1.w};
            float bv[8] = {b0.x, b0.y, b0.z, b0.w, b1.x, b1.y, b1.z, b1.w};
            #pragma unroll
            for (int i = 0; i < 8; i++)
                #pragma unroll
                for (int j = 0; j < 8; j++)
                    acc[i][j] = fmaf(av[i], bv[j], acc[i][j]);
        }
        __syncthreads();
    }

    float4 bb0 = *(const float4*)(bias + bn + tx * 8);
    float4 bb1 = *(const float4*)(bias + bn + tx * 8 + 4);
    #pragma unroll
    for (int i = 0; i < 8; i++) {
        int m = bm + ty * 8 + i;
        if (m < M) {
            float* Cp = C + (size_t)m * N + bn + tx * 8;
            float4 o0 = make_float4(acc[i][0] + bb0.x, acc[i][1] + bb0.y,
                                    acc[i][2] + bb0.z, acc[i][3] + bb0.w);
            float4 o1 = make_float4(acc[i][4] + bb1.x, acc[i][5] + bb1.y,
                                    acc[i][6] + bb1.z, acc[i][7] + bb1.w);
            *(float4*)Cp       = o0;
            *(float4*)(Cp + 4) = o1;
        }
    }
}

// ---------------- Kernel 3: GRU gates + MLP head + scatter ----------------
__global__ void __launch_bounds__(256) gates_mlp_kernel(
    const float* __restrict__ h, const int* __restrict__ i_obs,
    const float* __restrict__ m_w1, const float* __restrict__ m_b1,
    const float* __restrict__ m_w2, const float* __restrict__ m_b2,
    const float* __restrict__ m_w3, const float* __restrict__ m_b3,
    float* __restrict__ out_h)
{
    __shared__ float zin[2 * H];
    __shared__ float z1[32];
    __shared__ float z2[32];

    const int n = blockIdx.x;
    const int t = threadIdx.x;          // 0..255 == h-dim
    const int idx = i_obs[n];
    const size_t b = (size_t)n * G3;

    const float hg = h[(size_t)idx * H + t];
    {
        float r  = sigmoidf_(g_GI1[b + t]       + g_GH1[b + t]);
        float z  = sigmoidf_(g_GI1[b + H + t]   + g_GH1[b + H + t]);
        float ng = tanhf(g_GI1[b + 2 * H + t] + r * g_GH1[b + 2 * H + t]);
        zin[t] = (1.0f - z) * ng + z * hg;
    }
    {
        float r  = sigmoidf_(g_GI2[b + t]       + g_GH2[b + t]);
        float z  = sigmoidf_(g_GI2[b + H + t]   + g_GH2[b + H + t]);
        float ng = tanhf(g_GI2[b + 2 * H + t] + r * g_GH2[b + 2 * H + t]);
        zin[H + t] = (1.0f - z) * ng + z * hg;
    }
    __syncthreads();

    // MLP1: 512 -> 32, 8 threads per output, shuffle reduce
    {
        const int o = t >> 3, part = t & 7;
        const float* w = m_w1 + o * (2 * H);
        float s = 0.0f;
        #pragma unroll 8
        for (int k = part; k < 2 * H; k += 8) s = fmaf(zin[k], w[k], s);
        s += __shfl_down_sync(0xFFFFFFFFu, s, 4, 8);
        s += __shfl_down_sync(0xFFFFFFFFu, s, 2, 8);
        s += __shfl_down_sync(0xFFFFFFFFu, s, 1, 8);
        if (part == 0) z1[o] = fmaxf(s + m_b1[o], 0.0f);
    }
    __syncthreads();

    // MLP2: 32 -> 32
    if (t < 32) {
        const float* w = m_w2 + t * 32;
        float s = m_b2[t];
        #pragma unroll
        for (int k = 0; k < 32; k++) s = fmaf(z1[k], w[k], s);
        z2[t] = fmaxf(s, 0.0f);
    }
    __syncthreads();

    // MLP3: 32 -> 256, silu, scatter
    {
        const float* w = m_w3 + t * 32;
        float s = m_b3[t];
        #pragma unroll
        for (int k = 0; k < 32; k++) s = fmaf(z2[k], w[k], s);
        out_h[(size_t)idx * H + t] = s * sigmoidf_(s);
    }
}

// ---------------- launch ----------------
extern "C" void kernel_launch(void* const* d_in, const int* in_sizes, int n_in,
                              void* d_out, int out_size)
{
    const float* h         = (const float*)d_in[0];
    const float* p_obs     = (const float*)d_in[1];
    const float* X_obs     = (const float*)d_in[2];
    const float* M_obs     = (const float*)d_in[3];
    const float* adj       = (const float*)d_in[4];
    const int*   i_obs     = (const int*)  d_in[5];
    const float* w_prep    = (const float*)d_in[6];
    const float* w_prep2   = (const float*)d_in[7];
    const float* bias_prep = (const float*)d_in[8];
    const float* g1_w_ih   = (const float*)d_in[9];
    const float* g1_w_hh   = (const float*)d_in[10];
    const float* g1_b_ih   = (const float*)d_in[11];
    const float* g1_b_hh   = (const float*)d_in[12];
    const float* g2_w_ih   = (const float*)d_in[13];
    const float* g2_w_hh   = (const float*)d_in[14];
    const float* g2_b_ih   = (const float*)d_in[15];
    const float* g2_b_hh   = (const float*)d_in[16];
    const float* gcn_w1    = (const float*)d_in[17];
    const float* gcn_b1    = (const float*)d_in[18];
    const float* gcn_w2    = (const float*)d_in[19];
    const float* gcn_b2    = (const float*)d_in[20];
    const float* m_w1      = (const float*)d_in[21];
    const float* m_b1      = (const float*)d_in[22];
    const float* m_w2      = (const float*)d_in[23];
    const float* m_b2      = (const float*)d_in[24];
    const float* m_w3      = (const float*)d_in[25];
    const float* m_b3      = (const float*)d_in[26];

    float* out_h      = (float*)d_out;                                   // [100000,256]
    float* out_losses = (float*)d_out + (size_t)N_TOTAL * H;             // [50000,64]

    // h_new base = h
    cudaMemcpyAsync(out_h, h, (size_t)N_TOTAL * H * sizeof(float),
                    cudaMemcpyDeviceToDevice, 0);

    prep_kernel<<<N_OBS, 256>>>(p_obs, X_obs, M_obs, adj, w_prep, w_prep2, bias_prep,
                                gcn_w1, gcn_b1, gcn_w2, gcn_b2, out_losses);

    float *pX1, *pX2, *pGI1, *pGH1, *pGI2, *pGH2;
    cudaGetSymbolAddress((void**)&pX1,  g_X1);
    cudaGetSymbolAddress((void**)&pX2,  g_X2);
    cudaGetSymbolAddress((void**)&pGI1, g_GI1);
    cudaGetSymbolAddress((void**)&pGH1, g_GH1);
    cudaGetSymbolAddress((void**)&pGI2, g_GI2);
    cudaGetSymbolAddress((void**)&pGH2, g_GH2);

    dim3 gemm_grid(G3 / 128, (N_OBS + 127) / 128);
    sgemm_bias<<<gemm_grid, 256>>>(pX1, XK, nullptr, g1_w_ih, g1_b_ih, pGI1, N_OBS, XK);
    sgemm_bias<<<gemm_grid, 256>>>(h,   H,  i_obs,   g1_w_hh, g1_b_hh, pGH1, N_OBS, H);
    sgemm_bias<<<gemm_grid, 256>>>(pX2, XK, nullptr, g2_w_ih, g2_b_ih, pGI2, N_OBS, XK);
    sgemm_bias<<<gemm_grid, 256>>>(h,   H,  i_obs,   g2_w_hh, g2_b_hh, pGH2, N_OBS, H);

    gates_mlp_kernel<<<N_OBS, 256>>>(h, i_obs, m_w1, m_b1, m_w2, m_b2, m_w3, m_b3, out_h);
}

// round 7
// speedup vs baseline: 2.5746x; 2.5746x over previous
#include <cuda_runtime.h>
#include <cuda_bf16.h>
#include <cstdint>

#define N_OBS   50000
#define N_TOTAL 100000
#define F       64
#define P       16
#define H       256
#define G3      768        // 3*H
#define XK      1024       // F*P
#define TWO_LOG_LIK_C 1.8378770664093453f

// ---------------- scratch (static __device__ — no allocations) ----------------
__device__ __nv_bfloat16 g_X1h[(size_t)N_OBS * XK];
__device__ __nv_bfloat16 g_X1l[(size_t)N_OBS * XK];
__device__ __nv_bfloat16 g_X2h[(size_t)N_OBS * XK];
__device__ __nv_bfloat16 g_X2l[(size_t)N_OBS * XK];
__device__ __nv_bfloat16 g_Hgh[(size_t)N_OBS * H];
__device__ __nv_bfloat16 g_Hgl[(size_t)N_OBS * H];
__device__ __nv_bfloat16 g_W1ih_h[(size_t)G3 * XK];
__device__ __nv_bfloat16 g_W1ih_l[(size_t)G3 * XK];
__device__ __nv_bfloat16 g_W2ih_h[(size_t)G3 * XK];
__device__ __nv_bfloat16 g_W2ih_l[(size_t)G3 * XK];
__device__ __nv_bfloat16 g_W1hh_h[(size_t)G3 * H];
__device__ __nv_bfloat16 g_W1hh_l[(size_t)G3 * H];
__device__ __nv_bfloat16 g_W2hh_h[(size_t)G3 * H];
__device__ __nv_bfloat16 g_W2hh_l[(size_t)G3 * H];
__device__ float g_GI1[(size_t)N_OBS * G3];
__device__ float g_GH1[(size_t)N_OBS * G3];
__device__ float g_GI2[(size_t)N_OBS * G3];
__device__ float g_GH2[(size_t)N_OBS * G3];

__device__ __forceinline__ float sigmoidf_(float x) { return 1.0f / (1.0f + expf(-x)); }

__device__ __forceinline__ uint32_t smem_u32(const void* p) {
    uint32_t a;
    asm("{ .reg .u64 t; cvta.to.shared.u64 t, %1; cvt.u32.u64 %0, t; }" : "=r"(a) : "l"(p));
    return a;
}

#define SPLIT_BF16(v, hi, lo) do { \
    hi = __float2bfloat16(v);      \
    lo = __float2bfloat16((v) - __bfloat162float(hi)); } while (0)

// ---------------- Kernel 1: losses + factored GCN + prep feats (bf16 hi/lo out) ----------------
__global__ void __launch_bounds__(256) prep_kernel(
    const float* __restrict__ p_obs, const float* __restrict__ X_obs,
    const float* __restrict__ M_obs, const float* __restrict__ adj,
    const float* __restrict__ w_prep, const float* __restrict__ w_prep2,
    const float* __restrict__ bias_prep,
    const float* __restrict__ gcn_w1, const float* __restrict__ gcn_b1,
    const float* __restrict__ gcn_w2, const float* __restrict__ gcn_b2,
    float* __restrict__ losses_out)
{
    __shared__ float adj_s[F * 65];
    __shared__ float xs[F], means[F], lvs[F], errs[F], ms[F];
    __shared__ float axs[F], ss[F], hobs[F];

    const int n = blockIdx.x;
    const int t = threadIdx.x;

    for (int i = t; i < F * F; i += 256)
        adj_s[(i >> 6) * 65 + (i & 63)] = adj[i];

    if (t < F) {
        const int f = t;
        float x    = X_obs[n * F + f];
        float mean = p_obs[n * (2 * F) + f];
        float lv   = p_obs[n * (2 * F) + F + f];
        float m    = M_obs[n * F + f];
        float err  = (x - mean) * expf(-0.5f * lv);
        xs[f] = x; means[f] = mean; lvs[f] = lv; errs[f] = err; ms[f] = m;
        losses_out[n * F + f] = 0.5f * ((err * err + lv + TWO_LOG_LIK_C) * m);
    }
    __syncthreads();

    if (t < F) {
        const float* ar = adj_s + t * 65;
        float s = 0.0f;
        #pragma unroll 8
        for (int g = 0; g < F; g++) s += ar[g] * xs[g];
        axs[t] = s;
    }
    __syncthreads();

    if (t < F) {
        float a = axs[t];
        float acc = 0.0f;
        #pragma unroll
        for (int c = 0; c < 32; c++) {
            float v = fmaf(a, gcn_w1[c], gcn_b1[c]);
            acc = fmaf(gcn_w2[c], fmaxf(v, 0.0f), acc);
        }
        ss[t] = acc;
    }
    __syncthreads();

    if (t < F) {
        const float* ar = adj_s + t * 65;
        float s = gcn_b2[0];
        #pragma unroll 8
        for (int g = 0; g < F; g++) s += ar[g] * ss[g];
        hobs[t] = s;
    }
    __syncthreads();

    for (int i = t; i < XK; i += 256) {
        const int f = i >> 4, p = i & 15;
        const float* w = w_prep + f * (4 * P);
        float v = bias_prep[f * P + p];
        v = fmaf(xs[f],    w[p],          v);
        v = fmaf(means[f], w[P + p],      v);
        v = fmaf(lvs[f],   w[2 * P + p],  v);
        v = fmaf(errs[f],  w[3 * P + p],  v);
        v = fmaxf(v, 0.0f) * ms[f];
        __nv_bfloat16 hi, lo; SPLIT_BF16(v, hi, lo);
        g_X1h[(size_t)n * XK + i] = hi;
        g_X1l[(size_t)n * XK + i] = lo;
    }
    for (int i = t; i < XK; i += 256) {
        const int f = i >> 4, p = i & 15;
        const float* w = w_prep2 + f * (5 * P);
        float v = bias_prep[f * P + p];
        v = fmaf(xs[f],    w[p],          v);
        v = fmaf(hobs[f],  w[P + p],      v);
        v = fmaf(means[f], w[2 * P + p],  v);
        v = fmaf(lvs[f],   w[3 * P + p],  v);
        v = fmaf(errs[f],  w[4 * P + p],  v);
        v = fmaxf(v, 0.0f) * ms[f];
        __nv_bfloat16 hi, lo; SPLIT_BF16(v, hi, lo);
        g_X2h[(size_t)n * XK + i] = hi;
        g_X2l[(size_t)n * XK + i] = lo;
    }
}

// ---------------- split / gather-split helpers ----------------
__global__ void __launch_bounds__(256) split_kernel(
    const float* __restrict__ src, __nv_bfloat16* __restrict__ hi,
    __nv_bfloat16* __restrict__ lo, int n)
{
    int i = blockIdx.x * 256 + threadIdx.x;
    if (i < n) {
        float v = src[i];
        __nv_bfloat16 h, l; SPLIT_BF16(v, h, l);
        hi[i] = h; lo[i] = l;
    }
}

__global__ void __launch_bounds__(256) gather_split_kernel(
    const float* __restrict__ h, const int* __restrict__ i_obs,
    __nv_bfloat16* __restrict__ hi, __nv_bfloat16* __restrict__ lo)
{
    int n = blockIdx.x, t = threadIdx.x;
    int idx = i_obs[n];
    float v = h[(size_t)idx * H + t];
    __nv_bfloat16 hh, ll; SPLIT_BF16(v, hh, ll);
    hi[(size_t)n * H + t] = hh;
    lo[(size_t)n * H + t] = ll;
}

// ---------------- Kernel 2: HMMA bf16x3 GEMM  C[M,768] = A@B^T + bias ----------------
// CTA 128x128, BK=32 bf16, 256 thr (8 warps, warp tile 64x32), cp.async double buffer.
// Smem rows padded to 80B -> conflict-free ldmatrix (80*r mod 128 hits 8 distinct residues).
#define BM 128
#define BN 128
#define BKB 32
#define PITCH 80
#define STAGE_MAT (BM * PITCH)          // 10240 B per matrix
#define STAGE_BYTES (4 * STAGE_MAT)     // Ah, Al, Bh, Bl = 40960
#define GEMM_SMEM (2 * STAGE_BYTES)     // 81920

__device__ __forceinline__ void cp16(uint32_t dst, const void* src, bool pred) {
    asm volatile("cp.async.cg.shared.global [%0], [%1], 16, %2;"
                 :: "r"(dst), "l"(src), "r"(pred ? 16 : 0));
}
__device__ __forceinline__ void ldm_x4(uint32_t* r, uint32_t addr) {
    asm volatile("ldmatrix.sync.aligned.m8n8.x4.shared.b16 {%0,%1,%2,%3}, [%4];"
                 : "=r"(r[0]), "=r"(r[1]), "=r"(r[2]), "=r"(r[3]) : "r"(addr));
}
__device__ __forceinline__ void mma16816(float* c, const uint32_t* a, uint32_t b0, uint32_t b1) {
    asm volatile("mma.sync.aligned.m16n8k16.row.col.f32.bf16.bf16.f32 "
                 "{%0,%1,%2,%3}, {%4,%5,%6,%7}, {%8,%9}, {%0,%1,%2,%3};"
                 : "+f"(c[0]), "+f"(c[1]), "+f"(c[2]), "+f"(c[3])
                 : "r"(a[0]), "r"(a[1]), "r"(a[2]), "r"(a[3]), "r"(b0), "r"(b1));
}

__global__ void __launch_bounds__(256, 1) mma_gemm(
    const __nv_bfloat16* __restrict__ Ah, const __nv_bfloat16* __restrict__ Al,
    const __nv_bfloat16* __restrict__ Bh, const __nv_bfloat16* __restrict__ Bl,
    const float* __restrict__ bias, float* __restrict__ C, int M, int K)
{
    extern __shared__ char smem_raw[];
    const uint32_t su = smem_u32(smem_raw);

    const int t    = threadIdx.x;
    const int wid  = t >> 5;
    const int lane = t & 31;
    const int bm   = blockIdx.y * BM;
    const int bn   = blockIdx.x * BN;
    const int nk   = K / BKB;

    // warp tile: 2 (M) x 4 (N)
    const int wm = (wid & 1) * 64;
    const int wn = (wid >> 1) * 32;

    // ---- load mapping: thread -> (row, 16B chunk), 2 rows per matrix ----
    const int rowt  = t >> 2;       // 0..63
    const int chunk = t & 3;        // 16B chunk within 64B k-row

    const int garow0 = bm + rowt, garow1 = bm + rowt + 64;
    const bool p0 = garow0 < M, p1 = garow1 < M;
    const __nv_bfloat16* Ah0 = Ah + (size_t)(p0 ? garow0 : 0) * K + chunk * 8;
    const __nv_bfloat16* Ah1 = Ah + (size_t)(p1 ? garow1 : 0) * K + chunk * 8;
    const __nv_bfloat16* Al0 = Al + (size_t)(p0 ? garow0 : 0) * K + chunk * 8;
    const __nv_bfloat16* Al1 = Al + (size_t)(p1 ? garow1 : 0) * K + chunk * 8;
    const __nv_bfloat16* Bh0 = Bh + (size_t)(bn + rowt) * K + chunk * 8;
    const __nv_bfloat16* Bh1 = Bh + (size_t)(bn + rowt + 64) * K + chunk * 8;
    const __nv_bfloat16* Bl0 = Bl + (size_t)(bn + rowt) * K + chunk * 8;
    const __nv_bfloat16* Bl1 = Bl + (size_t)(bn + rowt + 64) * K + chunk * 8;

    const uint32_t d0 = (uint32_t)rowt * PITCH + (uint32_t)chunk * 16;
    const uint32_t d1 = d0 + 64 * PITCH;

    auto load_stage = [&](int kb, int buf) {
        const uint32_t base = su + buf * STAGE_BYTES;
        const int ke = kb * BKB;
        cp16(base + d0,                 Ah0 + ke, p0);
        cp16(base + d1,                 Ah1 + ke, p1);
        cp16(base + STAGE_MAT + d0,     Al0 + ke, p0);
        cp16(base + STAGE_MAT + d1,     Al1 + ke, p1);
        cp16(base + 2 * STAGE_MAT + d0, Bh0 + ke, true);
        cp16(base + 2 * STAGE_MAT + d1, Bh1 + ke, true);
        cp16(base + 3 * STAGE_MAT + d0, Bl0 + ke, true);
        cp16(base + 3 * STAGE_MAT + d1, Bl1 + ke, true);
    };

    float acc[4][4][4];
    #pragma unroll
    for (int i = 0; i < 4; i++)
        #pragma unroll
        for (int j = 0; j < 4; j++)
            #pragma unroll
            for (int k = 0; k < 4; k++) acc[i][j][k] = 0.0f;

    load_stage(0, 0);
    asm volatile("cp.async.commit_group;");

    int buf = 0;
    for (int kb = 0; kb < nk; kb++) {
        if (kb + 1 < nk) {
            load_stage(kb + 1, buf ^ 1);
            asm volatile("cp.async.commit_group;");
            asm volatile("cp.async.wait_group 1;");
        } else {
            asm volatile("cp.async.wait_group 0;");
        }
        __syncthreads();

        const uint32_t sa = su + buf * STAGE_BYTES;
        const uint32_t sb = sa + 2 * STAGE_MAT;

        #pragma unroll
        for (int ks = 0; ks < 2; ks++) {
            const uint32_t kbyte = (uint32_t)ks * 32;
            // A fragments (4 m-frags, hi & lo)
            uint32_t a_h[4][4], a_l[4][4];
            const uint32_t arow = (uint32_t)(wm + (lane & 15)) * PITCH
                                + kbyte + ((uint32_t)(lane >> 4) << 4);
            #pragma unroll
            for (int mf = 0; mf < 4; mf++) {
                uint32_t ad = sa + arow + (uint32_t)mf * 16 * PITCH;
                ldm_x4(a_h[mf], ad);
                ldm_x4(a_l[mf], ad + STAGE_MAT);
            }
            // B fragments (2 x 16-n groups, hi & lo)
            uint32_t b_h[2][4], b_l[2][4];
            const uint32_t brow = (uint32_t)(wn + (((lane >> 3) & 2) << 2) + (lane & 7)) * PITCH
                                + kbyte + (((uint32_t)(lane >> 3) & 1) << 4);
            #pragma unroll
            for (int nfp = 0; nfp < 2; nfp++) {
                uint32_t bd = sb + brow + (uint32_t)nfp * 16 * PITCH;
                ldm_x4(b_h[nfp], bd);
                ldm_x4(b_l[nfp], bd + STAGE_MAT);
            }
            // 3-term compensated MMA: hh + hl + lh
            #pragma unroll
            for (int mf = 0; mf < 4; mf++)
                #pragma unroll
                for (int nf = 0; nf < 4; nf++) {
                    const int nfp = nf >> 1, sub = (nf & 1) * 2;
                    mma16816(acc[mf][nf], a_h[mf], b_h[nfp][sub], b_h[nfp][sub + 1]);
                    mma16816(acc[mf][nf], a_h[mf], b_l[nfp][sub], b_l[nfp][sub + 1]);
                    mma16816(acc[mf][nf], a_l[mf], b_h[nfp][sub], b_h[nfp][sub + 1]);
                }
        }
        __syncthreads();
        buf ^= 1;
    }

    // ---- epilogue: bias + store ----
    #pragma unroll
    for (int mf = 0; mf < 4; mf++) {
        const int r0 = bm + wm + mf * 16 + (lane >> 2);
        #pragma unroll
        for (int nf = 0; nf < 4; nf++) {
            const int col = bn + wn + nf * 8 + (lane & 3) * 2;
            const float b0 = bias[col], b1 = bias[col + 1];
            if (r0 < M) {
                float2 v = make_float2(acc[mf][nf][0] + b0, acc[mf][nf][1] + b1);
                *(float2*)(C + (size_t)r0 * G3 + col) = v;
            }
            if (r0 + 8 < M) {
                float2 v = make_float2(acc[mf][nf][2] + b0, acc[mf][nf][3] + b1);
                *(float2*)(C + (size_t)(r0 + 8) * G3 + col) = v;
            }
        }
    }
}

// ---------------- Kernel 3: GRU gates + MLP head + scatter ----------------
__global__ void __launch_bounds__(256) gates_mlp_kernel(
    const float* __restrict__ h, const int* __restrict__ i_obs,
    const float* __restrict__ m_w1, const float* __restrict__ m_b1,
    const float* __restrict__ m_w2, const float* __restrict__ m_b2,
    const float* __restrict__ m_w3, const float* __restrict__ m_b3,
    float* __restrict__ out_h)
{
    __shared__ float zin[2 * H];
    __shared__ float z1[32];
    __shared__ float z2[32];

    const int n = blockIdx.x;
    const int t = threadIdx.x;
    const int idx = i_obs[n];
    const size_t b = (size_t)n * G3;

    const float hg = h[(size_t)idx * H + t];
    {
        float r  = sigmoidf_(g_GI1[b + t]       + g_GH1[b + t]);
        float z  = sigmoidf_(g_GI1[b + H + t]   + g_GH1[b + H + t]);
        float ng = tanhf(g_GI1[b + 2 * H + t] + r * g_GH1[b + 2 * H + t]);
        zin[t] = (1.0f - z) * ng + z * hg;
    }
    {
        float r  = sigmoidf_(g_GI2[b + t]       + g_GH2[b + t]);
        float z  = sigmoidf_(g_GI2[b + H + t]   + g_GH2[b + H + t]);
        float ng = tanhf(g_GI2[b + 2 * H + t] + r * g_GH2[b + 2 * H + t]);
        zin[H + t] = (1.0f - z) * ng + z * hg;
    }
    __syncthreads();

    {
        const int o = t >> 3, part = t & 7;
        const float* w = m_w1 + o * (2 * H);
        float s = 0.0f;
        #pragma unroll 8
        for (int k = part; k < 2 * H; k += 8) s = fmaf(zin[k], w[k], s);
        s += __shfl_down_sync(0xFFFFFFFFu, s, 4, 8);
        s += __shfl_down_sync(0xFFFFFFFFu, s, 2, 8);
        s += __shfl_down_sync(0xFFFFFFFFu, s, 1, 8);
        if (part == 0) z1[o] = fmaxf(s + m_b1[o], 0.0f);
    }
    __syncthreads();

    if (t < 32) {
        const float* w = m_w2 + t * 32;
        float s = m_b2[t];
        #pragma unroll
        for (int k = 0; k < 32; k++) s = fmaf(z1[k], w[k], s);
        z2[t] = fmaxf(s, 0.0f);
    }
    __syncthreads();

    {
        const float* w = m_w3 + t * 32;
        float s = m_b3[t];
        #pragma unroll
        for (int k = 0; k < 32; k++) s = fmaf(z2[k], w[k], s);
        out_h[(size_t)idx * H + t] = s * sigmoidf_(s);
    }
}

// ---------------- launch ----------------
extern "C" void kernel_launch(void* const* d_in, const int* in_sizes, int n_in,
                              void* d_out, int out_size)
{
    const float* h         = (const float*)d_in[0];
    const float* p_obs     = (const float*)d_in[1];
    const float* X_obs     = (const float*)d_in[2];
    const float* M_obs     = (const float*)d_in[3];
    const float* adj       = (const float*)d_in[4];
    const int*   i_obs     = (const int*)  d_in[5];
    const float* w_prep    = (const float*)d_in[6];
    const float* w_prep2   = (const float*)d_in[7];
    const float* bias_prep = (const float*)d_in[8];
    const float* g1_w_ih   = (const float*)d_in[9];
    const float* g1_w_hh   = (const float*)d_in[10];
    const float* g1_b_ih   = (const float*)d_in[11];
    const float* g1_b_hh   = (const float*)d_in[12];
    const float* g2_w_ih   = (const float*)d_in[13];
    const float* g2_w_hh   = (const float*)d_in[14];
    const float* g2_b_ih   = (const float*)d_in[15];
    const float* g2_b_hh   = (const float*)d_in[16];
    const float* gcn_w1    = (const float*)d_in[17];
    const float* gcn_b1    = (const float*)d_in[18];
    const float* gcn_w2    = (const float*)d_in[19];
    const float* gcn_b2    = (const float*)d_in[20];
    const float* m_w1      = (const float*)d_in[21];
    const float* m_b1      = (const float*)d_in[22];
    const float* m_w2      = (const float*)d_in[23];
    const float* m_b2      = (const float*)d_in[24];
    const float* m_w3      = (const float*)d_in[25];
    const float* m_b3      = (const float*)d_in[26];

    float* out_h      = (float*)d_out;                           // [100000,256]
    float* out_losses = (float*)d_out + (size_t)N_TOTAL * H;     // [50000,64]

    cudaMemcpyAsync(out_h, h, (size_t)N_TOTAL * H * sizeof(float),
                    cudaMemcpyDeviceToDevice, 0);

    prep_kernel<<<N_OBS, 256>>>(p_obs, X_obs, M_obs, adj, w_prep, w_prep2, bias_prep,
                                gcn_w1, gcn_b1, gcn_w2, gcn_b2, out_losses);

    __nv_bfloat16 *pX1h, *pX1l, *pX2h, *pX2l, *pHgh, *pHgl;
    __nv_bfloat16 *pW1ih_h, *pW1ih_l, *pW2ih_h, *pW2ih_l;
    __nv_bfloat16 *pW1hh_h, *pW1hh_l, *pW2hh_h, *pW2hh_l;
    float *pGI1, *pGH1, *pGI2, *pGH2;
    cudaGetSymbolAddress((void**)&pX1h, g_X1h);  cudaGetSymbolAddress((void**)&pX1l, g_X1l);
    cudaGetSymbolAddress((void**)&pX2h, g_X2h);  cudaGetSymbolAddress((void**)&pX2l, g_X2l);
    cudaGetSymbolAddress((void**)&pHgh, g_Hgh);  cudaGetSymbolAddress((void**)&pHgl, g_Hgl);
    cudaGetSymbolAddress((void**)&pW1ih_h, g_W1ih_h); cudaGetSymbolAddress((void**)&pW1ih_l, g_W1ih_l);
    cudaGetSymbolAddress((void**)&pW2ih_h, g_W2ih_h); cudaGetSymbolAddress((void**)&pW2ih_l, g_W2ih_l);
    cudaGetSymbolAddress((void**)&pW1hh_h, g_W1hh_h); cudaGetSymbolAddress((void**)&pW1hh_l, g_W1hh_l);
    cudaGetSymbolAddress((void**)&pW2hh_h, g_W2hh_h); cudaGetSymbolAddress((void**)&pW2hh_l, g_W2hh_l);
    cudaGetSymbolAddress((void**)&pGI1, g_GI1);  cudaGetSymbolAddress((void**)&pGH1, g_GH1);
    cudaGetSymbolAddress((void**)&pGI2, g_GI2);  cudaGetSymbolAddress((void**)&pGH2, g_GH2);

    split_kernel<<<(G3 * XK + 255) / 256, 256>>>(g1_w_ih, pW1ih_h, pW1ih_l, G3 * XK);
    split_kernel<<<(G3 * XK + 255) / 256, 256>>>(g2_w_ih, pW2ih_h, pW2ih_l, G3 * XK);
    split_kernel<<<(G3 * H + 255) / 256, 256>>>(g1_w_hh, pW1hh_h, pW1hh_l, G3 * H);
    split_kernel<<<(G3 * H + 255) / 256, 256>>>(g2_w_hh, pW2hh_h, pW2hh_l, G3 * H);
    gather_split_kernel<<<N_OBS, 256>>>(h, i_obs, pHgh, pHgl);

    cudaFuncSetAttribute(mma_gemm, cudaFuncAttributeMaxDynamicSharedMemorySize, GEMM_SMEM);

    dim3 gg(G3 / 128, (N_OBS + 127) / 128);
    mma_gemm<<<gg, 256, GEMM_SMEM>>>(pX1h, pX1l, pW1ih_h, pW1ih_l, g1_b_ih, pGI1, N_OBS, XK);
    mma_gemm<<<gg, 256, GEMM_SMEM>>>(pHgh, pHgl, pW1hh_h, pW1hh_l, g1_b_hh, pGH1, N_OBS, H);
    mma_gemm<<<gg, 256, GEMM_SMEM>>>(pX2h, pX2l, pW2ih_h, pW2ih_l, g2_b_ih, pGI2, N_OBS, XK);
    mma_gemm<<<gg, 256, GEMM_SMEM>>>(pHgh, pHgl, pW2hh_h, pW2hh_l, g2_b_hh, pGH2, N_OBS, H);

    gates_mlp_kernel<<<N_OBS, 256>>>(h, i_obs, m_w1, m_b1, m_w2, m_b2, m_w3, m_b3, out_h);
}

// round 8
// speedup vs baseline: 3.7202x; 1.4450x over previous
#include <cuda_runtime.h>
#include <cuda_bf16.h>
#include <cstdint>

#define N_OBS   50000
#define N_TOTAL 100000
#define F       64
#define P       16
#define H       256
#define G3      768        // 3*H
#define XK      1024       // F*P
#define TWO_LOG_LIK_C 1.8378770664093453f

// ---------------- scratch (static __device__ — no allocations) ----------------
__device__ __nv_bfloat16 g_X1h[(size_t)N_OBS * XK];
__device__ __nv_bfloat16 g_X1l[(size_t)N_OBS * XK];
__device__ __nv_bfloat16 g_X2h[(size_t)N_OBS * XK];
__device__ __nv_bfloat16 g_X2l[(size_t)N_OBS * XK];
__device__ __nv_bfloat16 g_Hgh[(size_t)N_OBS * H];
__device__ __nv_bfloat16 g_Hgl[(size_t)N_OBS * H];
__device__ __nv_bfloat16 g_W1ih_h[(size_t)G3 * XK];
__device__ __nv_bfloat16 g_W1ih_l[(size_t)G3 * XK];
__device__ __nv_bfloat16 g_W2ih_h[(size_t)G3 * XK];
__device__ __nv_bfloat16 g_W2ih_l[(size_t)G3 * XK];
__device__ __nv_bfloat16 g_W1hh_h[(size_t)G3 * H];
__device__ __nv_bfloat16 g_W1hh_l[(size_t)G3 * H];
__device__ __nv_bfloat16 g_W2hh_h[(size_t)G3 * H];
__device__ __nv_bfloat16 g_W2hh_l[(size_t)G3 * H];
__device__ float g_GI1[(size_t)N_OBS * G3];
__device__ float g_GH1[(size_t)N_OBS * G3];
__device__ float g_GI2[(size_t)N_OBS * G3];
__device__ float g_GH2[(size_t)N_OBS * G3];
__device__ float g_S   [(size_t)N_OBS * F];
__device__ float g_HOBS[(size_t)N_OBS * F];

__device__ __forceinline__ float sigmoidf_(float x) { return 1.0f / (1.0f + expf(-x)); }

__device__ __forceinline__ uint32_t smem_u32(const void* p) {
    uint32_t a;
    asm("{ .reg .u64 t; cvta.to.shared.u64 t, %1; cvt.u32.u64 %0, t; }" : "=r"(a) : "l"(p));
    return a;
}

#define SPLIT_BF16(v, hi, lo) do { \
    hi = __float2bfloat16(v);      \
    lo = __float2bfloat16((v) - __bfloat162float(hi)); } while (0)

// ---------------- GCN as two 64-wide GEMM passes over adj ----------------
// mode 0: Out[n,f] = s(ax)   where ax = sum_g adj[f,g]*In[n,g],
//         s(a) = sum_c w2[c]*relu(a*w1[c]+b1[c])
// mode 1: Out[n,f] = sum_g adj[f,g]*In[n,g] + b2
__global__ void __launch_bounds__(256) gcn_gemm(
    const float* __restrict__ In, const float* __restrict__ adj,
    const float* __restrict__ gw1, const float* __restrict__ gb1,
    const float* __restrict__ gw2, const float* __restrict__ gb2,
    float* __restrict__ Out, int mode)
{
    __shared__ float adj_s[F * 65];
    __shared__ float xrow[4][F];
    const int t = threadIdx.x;
    for (int i = t; i < F * F; i += 256)
        adj_s[(i >> 6) * 65 + (i & 63)] = adj[i];
    __syncthreads();

    const int f  = t & 63;
    const int g4 = t >> 6;
    const int base = blockIdx.x * 128;

    for (int it = 0; it < 32; it++) {
        const int r = base + it * 4 + g4;
        if (r < N_OBS) xrow[g4][f] = In[(size_t)r * F + f];
        __syncthreads();
        if (r < N_OBS) {
            const float* ar = adj_s + f * 65;
            float acc = 0.0f;
            #pragma unroll 16
            for (int g = 0; g < F; g++) acc = fmaf(ar[g], xrow[g4][g], acc);
            if (mode == 0) {
                float s = 0.0f;
                #pragma unroll
                for (int c = 0; c < 32; c++) {
                    float v = fmaf(acc, gw1[c], gb1[c]);
                    s = fmaf(gw2[c], fmaxf(v, 0.0f), s);
                }
                Out[(size_t)r * F + f] = s;
            } else {
                Out[(size_t)r * F + f] = acc + gb2[0];
            }
        }
        __syncthreads();
    }
}

// ---------------- Kernel 1: losses + prep feats (bf16 hi/lo out) ----------------
__global__ void __launch_bounds__(256) prep_kernel(
    const float* __restrict__ p_obs, const float* __restrict__ X_obs,
    const float* __restrict__ M_obs, const float* __restrict__ hobs_g,
    const float* __restrict__ w_prep, const float* __restrict__ w_prep2,
    const float* __restrict__ bias_prep,
    float* __restrict__ losses_out)
{
    __shared__ float xs[F], means[F], lvs[F], errs[F], ms[F];

    const int n = blockIdx.x;
    const int t = threadIdx.x;

    if (t < F) {
        const int f = t;
        float x    = X_obs[n * F + f];
        float mean = p_obs[n * (2 * F) + f];
        float lv   = p_obs[n * (2 * F) + F + f];
        float m    = M_obs[n * F + f];
        float err  = (x - mean) * expf(-0.5f * lv);
        xs[f] = x; means[f] = mean; lvs[f] = lv; errs[f] = err; ms[f] = m;
        losses_out[n * F + f] = 0.5f * ((err * err + lv + TWO_LOG_LIK_C) * m);
    }
    __syncthreads();

    for (int i = t; i < XK; i += 256) {
        const int f = i >> 4, p = i & 15;
        const float* w = w_prep + f * (4 * P);
        float v = bias_prep[f * P + p];
        v = fmaf(xs[f],    w[p],          v);
        v = fmaf(means[f], w[P + p],      v);
        v = fmaf(lvs[f],   w[2 * P + p],  v);
        v = fmaf(errs[f],  w[3 * P + p],  v);
        v = fmaxf(v, 0.0f) * ms[f];
        __nv_bfloat16 hi, lo; SPLIT_BF16(v, hi, lo);
        g_X1h[(size_t)n * XK + i] = hi;
        g_X1l[(size_t)n * XK + i] = lo;
    }
    for (int i = t; i < XK; i += 256) {
        const int f = i >> 4, p = i & 15;
        const float* w = w_prep2 + f * (5 * P);
        float v = bias_prep[f * P + p];
        v = fmaf(xs[f],            w[p],          v);
        v = fmaf(hobs_g[n * F + f], w[P + p],     v);
        v = fmaf(means[f], w[2 * P + p],  v);
        v = fmaf(lvs[f],   w[3 * P + p],  v);
        v = fmaf(errs[f],  w[4 * P + p],  v);
        v = fmaxf(v, 0.0f) * ms[f];
        __nv_bfloat16 hi, lo; SPLIT_BF16(v, hi, lo);
        g_X2h[(size_t)n * XK + i] = hi;
        g_X2l[(size_t)n * XK + i] = lo;
    }
}

// ---------------- split / gather-split helpers ----------------
__global__ void __launch_bounds__(256) split_kernel(
    const float* __restrict__ src, __nv_bfloat16* __restrict__ hi,
    __nv_bfloat16* __restrict__ lo, int n)
{
    int i = blockIdx.x * 256 + threadIdx.x;
    if (i < n) {
        float v = src[i];
        __nv_bfloat16 h, l; SPLIT_BF16(v, h, l);
        hi[i] = h; lo[i] = l;
    }
}

__global__ void __launch_bounds__(256) gather_split_kernel(
    const float* __restrict__ h, const int* __restrict__ i_obs,
    __nv_bfloat16* __restrict__ hi, __nv_bfloat16* __restrict__ lo)
{
    int n = blockIdx.x, t = threadIdx.x;
    int idx = i_obs[n];
    float v = h[(size_t)idx * H + t];
    __nv_bfloat16 hh, ll; SPLIT_BF16(v, hh, ll);
    hi[(size_t)n * H + t] = hh;
    lo[(size_t)n * H + t] = ll;
}

// ---------------- Kernel 2: HMMA bf16x3 GEMM, 3-stage cp.async ring ----------------
#define BM 128
#define BN 128
#define BKB 32
#define PITCH 80
#define STAGE_MAT (BM * PITCH)          // 10240 B per matrix
#define STAGE_BYTES (4 * STAGE_MAT)     // Ah, Al, Bh, Bl = 40960
#define NSTAGE 3
#define GEMM_SMEM (NSTAGE * STAGE_BYTES)  // 122880

__device__ __forceinline__ void cp16(uint32_t dst, const void* src, bool pred) {
    asm volatile("cp.async.cg.shared.global [%0], [%1], 16, %2;"
                 :: "r"(dst), "l"(src), "r"(pred ? 16 : 0));
}
__device__ __forceinline__ void ldm_x4(uint32_t* r, uint32_t addr) {
    asm volatile("ldmatrix.sync.aligned.m8n8.x4.shared.b16 {%0,%1,%2,%3}, [%4];"
                 : "=r"(r[0]), "=r"(r[1]), "=r"(r[2]), "=r"(r[3]) : "r"(addr));
}
__device__ __forceinline__ void mma16816(float* c, const uint32_t* a, uint32_t b0, uint32_t b1) {
    asm volatile("mma.sync.aligned.m16n8k16.row.col.f32.bf16.bf16.f32 "
                 "{%0,%1,%2,%3}, {%4,%5,%6,%7}, {%8,%9}, {%0,%1,%2,%3};"
                 : "+f"(c[0]), "+f"(c[1]), "+f"(c[2]), "+f"(c[3])
                 : "r"(a[0]), "r"(a[1]), "r"(a[2]), "r"(a[3]), "r"(b0), "r"(b1));
}

__global__ void __launch_bounds__(256, 1) mma_gemm(
    const __nv_bfloat16* __restrict__ Ah, const __nv_bfloat16* __restrict__ Al,
    const __nv_bfloat16* __restrict__ Bh, const __nv_bfloat16* __restrict__ Bl,
    const float* __restrict__ bias, float* __restrict__ C, int M, int K)
{
    extern __shared__ char smem_raw[];
    const uint32_t su = smem_u32(smem_raw);

    const int t    = threadIdx.x;
    const int wid  = t >> 5;
    const int lane = t & 31;
    const int bm   = blockIdx.y * BM;
    const int bn   = blockIdx.x * BN;
    const int nk   = K / BKB;

    const int wm = (wid & 1) * 64;
    const int wn = (wid >> 1) * 32;

    const int rowt  = t >> 2;
    const int chunk = t & 3;

    const int garow0 = bm + rowt, garow1 = bm + rowt + 64;
    const bool p0 = garow0 < M, p1 = garow1 < M;
    const __nv_bfloat16* Ah0 = Ah + (size_t)(p0 ? garow0 : 0) * K + chunk * 8;
    const __nv_bfloat16* Ah1 = Ah + (size_t)(p1 ? garow1 : 0) * K + chunk * 8;
    const __nv_bfloat16* Al0 = Al + (size_t)(p0 ? garow0 : 0) * K + chunk * 8;
    const __nv_bfloat16* Al1 = Al + (size_t)(p1 ? garow1 : 0) * K + chunk * 8;
    const __nv_bfloat16* Bh0 = Bh + (size_t)(bn + rowt) * K + chunk * 8;
    const __nv_bfloat16* Bh1 = Bh + (size_t)(bn + rowt + 64) * K + chunk * 8;
    const __nv_bfloat16* Bl0 = Bl + (size_t)(bn + rowt) * K + chunk * 8;
    const __nv_bfloat16* Bl1 = Bl + (size_t)(bn + rowt + 64) * K + chunk * 8;

    const uint32_t d0 = (uint32_t)rowt * PITCH + (uint32_t)chunk * 16;
    const uint32_t d1 = d0 + 64 * PITCH;

    auto load_stage = [&](int kb, int buf) {
        const uint32_t base = su + buf * STAGE_BYTES;
        const int ke = kb * BKB;
        cp16(base + d0,                 Ah0 + ke, p0);
        cp16(base + d1,                 Ah1 + ke, p1);
        cp16(base + STAGE_MAT + d0,     Al0 + ke, p0);
        cp16(base + STAGE_MAT + d1,     Al1 + ke, p1);
        cp16(base + 2 * STAGE_MAT + d0, Bh0 + ke, true);
        cp16(base + 2 * STAGE_MAT + d1, Bh1 + ke, true);
        cp16(base + 3 * STAGE_MAT + d0, Bl0 + ke, true);
        cp16(base + 3 * STAGE_MAT + d1, Bl1 + ke, true);
        asm volatile("cp.async.commit_group;");
    };

    float acc[4][4][4];
    #pragma unroll
    for (int i = 0; i < 4; i++)
        #pragma unroll
        for (int j = 0; j < 4; j++)
            #pragma unroll
            for (int k = 0; k < 4; k++) acc[i][j][k] = 0.0f;

    load_stage(0, 0);
    load_stage(1, 1);

    int buf = 0;
    for (int kb = 0; kb < nk; kb++) {
        if (kb + 1 < nk) asm volatile("cp.async.wait_group 1;");
        else             asm volatile("cp.async.wait_group 0;");
        __syncthreads();

        const uint32_t sa = su + buf * STAGE_BYTES;
        const uint32_t sb = sa + 2 * STAGE_MAT;

        // prefetch next+1 stage into the buffer freed last iteration
        if (kb + 2 < nk) {
            int lbuf = buf + 2; if (lbuf >= NSTAGE) lbuf -= NSTAGE;
            load_stage(kb + 2, lbuf);
        }

        #pragma unroll
        for (int ks = 0; ks < 2; ks++) {
            const uint32_t kbyte = (uint32_t)ks * 32;
            uint32_t a_h[4][4], a_l[4][4];
            const uint32_t arow = (uint32_t)(wm + (lane & 15)) * PITCH
                                + kbyte + ((uint32_t)(lane >> 4) << 4);
            #pragma unroll
            for (int mf = 0; mf < 4; mf++) {
                uint32_t ad = sa + arow + (uint32_t)mf * 16 * PITCH;
                ldm_x4(a_h[mf], ad);
                ldm_x4(a_l[mf], ad + STAGE_MAT);
            }
            uint32_t b_h[2][4], b_l[2][4];
            const uint32_t brow = (uint32_t)(wn + (((lane >> 3) & 2) << 2) + (lane & 7)) * PITCH
                                + kbyte + (((uint32_t)(lane >> 3) & 1) << 4);
            #pragma unroll
            for (int nfp = 0; nfp < 2; nfp++) {
                uint32_t bd = sb + brow + (uint32_t)nfp * 16 * PITCH;
                ldm_x4(b_h[nfp], bd);
                ldm_x4(b_l[nfp], bd + STAGE_MAT);
            }
            #pragma unroll
            for (int mf = 0; mf < 4; mf++)
                #pragma unroll
                for (int nf = 0; nf < 4; nf++) {
                    const int nfp = nf >> 1, sub = (nf & 1) * 2;
                    mma16816(acc[mf][nf], a_h[mf], b_h[nfp][sub], b_h[nfp][sub + 1]);
                    mma16816(acc[mf][nf], a_h[mf], b_l[nfp][sub], b_l[nfp][sub + 1]);
                    mma16816(acc[mf][nf], a_l[mf], b_h[nfp][sub], b_h[nfp][sub + 1]);
                }
        }
        buf = buf + 1; if (buf >= NSTAGE) buf -= NSTAGE;
    }

    #pragma unroll
    for (int mf = 0; mf < 4; mf++) {
        const int r0 = bm + wm + mf * 16 + (lane >> 2);
        #pragma unroll
        for (int nf = 0; nf < 4; nf++) {
            const int col = bn + wn + nf * 8 + (lane & 3) * 2;
            const float b0 = bias[col], b1 = bias[col + 1];
            if (r0 < M) {
                float2 v = make_float2(acc[mf][nf][0] + b0, acc[mf][nf][1] + b1);
                *(float2*)(C + (size_t)r0 * G3 + col) = v;
            }
            if (r0 + 8 < M) {
                float2 v = make_float2(acc[mf][nf][2] + b0, acc[mf][nf][3] + b1);
                *(float2*)(C + (size_t)(r0 + 8) * G3 + col) = v;
            }
        }
    }
}

// ---------------- Kernel 3: GRU gates + MLP head (weights cached in smem) ----------------
#define GR 16                         // rows per block
#define W1_OFF 0                      // 32*512 floats = 65536 B
#define W3_OFF (W1_OFF + 32 * 512)    // 256*33 floats = 33792 B
#define W2_OFF (W3_OFF + 256 * 33)    // 32*33 floats = 4224 B
#define ZIN_OFF (W2_OFF + 32 * 33)
#define Z1_OFF  (ZIN_OFF + 512)
#define Z2_OFF  (Z1_OFF + 32)
#define GATES_SMEM ((Z2_OFF + 32) * 4)

__global__ void __launch_bounds__(256) gates_mlp_kernel(
    const float* __restrict__ h, const int* __restrict__ i_obs,
    const float* __restrict__ m_w1, const float* __restrict__ m_b1,
    const float* __restrict__ m_w2, const float* __restrict__ m_b2,
    const float* __restrict__ m_w3, const float* __restrict__ m_b3,
    float* __restrict__ out_h)
{
    extern __shared__ float sm[];
    float* w1s = sm + W1_OFF;
    float* w3s = sm + W3_OFF;
    float* w2s = sm + W2_OFF;
    float* zin = sm + ZIN_OFF;
    float* z1  = sm + Z1_OFF;
    float* z2  = sm + Z2_OFF;

    const int t    = threadIdx.x;
    const int wid  = t >> 5;
    const int lane = t & 31;

    for (int i = t; i < 32 * 512; i += 256) w1s[i] = m_w1[i];
    for (int i = t; i < 256 * 32; i += 256) w3s[(i >> 5) * 33 + (i & 31)] = m_w3[i];
    for (int i = t; i < 32 * 32;  i += 256) w2s[(i >> 5) * 33 + (i & 31)] = m_w2[i];
    __syncthreads();

    const int n0 = blockIdx.x * GR;
    for (int r = 0; r < GR; r++) {
        const int n = n0 + r;
        const int idx = i_obs[n];
        const size_t b = (size_t)n * G3;

        const float hg = h[(size_t)idx * H + t];
        {
            float rr = sigmoidf_(g_GI1[b + t]       + g_GH1[b + t]);
            float zz = sigmoidf_(g_GI1[b + H + t]   + g_GH1[b + H + t]);
            float ng = tanhf(g_GI1[b + 2 * H + t] + rr * g_GH1[b + 2 * H + t]);
            zin[t] = (1.0f - zz) * ng + zz * hg;
        }
        {
            float rr = sigmoidf_(g_GI2[b + t]       + g_GH2[b + t]);
            float zz = sigmoidf_(g_GI2[b + H + t]   + g_GH2[b + H + t]);
            float ng = tanhf(g_GI2[b + 2 * H + t] + rr * g_GH2[b + 2 * H + t]);
            zin[H + t] = (1.0f - zz) * ng + zz * hg;
        }
        __syncthreads();

        // MLP1: 512 -> 32; warp wid computes outputs 4*wid..4*wid+3, full-warp reduce
        #pragma unroll
        for (int q = 0; q < 4; q++) {
            const int o = 4 * wid + q;
            const float* wrow = w1s + o * 512;
            float s = 0.0f;
            #pragma unroll
            for (int j = 0; j < 16; j++)
                s = fmaf(zin[lane + 32 * j], wrow[lane + 32 * j], s);
            #pragma unroll
            for (int off = 16; off > 0; off >>= 1)
                s += __shfl_xor_sync(0xFFFFFFFFu, s, off);
            if (lane == 0) z1[o] = fmaxf(s + m_b1[o], 0.0f);
        }
        __syncthreads();

        // MLP2: 32 -> 32
        if (t < 32) {
            const float* w = w2s + t * 33;
            float s = m_b2[t];
            #pragma unroll
            for (int k = 0; k < 32; k++) s = fmaf(z1[k], w[k], s);
            z2[t] = fmaxf(s, 0.0f);
        }
        __syncthreads();

        // MLP3: 32 -> 256, silu, scatter
        {
            const float* w = w3s + t * 33;
            float s = m_b3[t];
            #pragma unroll
            for (int k = 0; k < 32; k++) s = fmaf(z2[k], w[k], s);
            out_h[(size_t)idx * H + t] = s * sigmoidf_(s);
        }
        __syncthreads();
    }
}

// ---------------- launch ----------------
extern "C" void kernel_launch(void* const* d_in, const int* in_sizes, int n_in,
                              void* d_out, int out_size)
{
    const float* h         = (const float*)d_in[0];
    const float* p_obs     = (const float*)d_in[1];
    const float* X_obs     = (const float*)d_in[2];
    const float* M_obs     = (const float*)d_in[3];
    const float* adj       = (const float*)d_in[4];
    const int*   i_obs     = (const int*)  d_in[5];
    const float* w_prep    = (const float*)d_in[6];
    const float* w_prep2   = (const float*)d_in[7];
    const float* bias_prep = (const float*)d_in[8];
    const float* g1_w_ih   = (const float*)d_in[9];
    const float* g1_w_hh   = (const float*)d_in[10];
    const float* g1_b_ih   = (const float*)d_in[11];
    const float* g1_b_hh   = (const float*)d_in[12];
    const float* g2_w_ih   = (const float*)d_in[13];
    const float* g2_w_hh   = (const float*)d_in[14];
    const float* g2_b_ih   = (const float*)d_in[15];
    const float* g2_b_hh   = (const float*)d_in[16];
    const float* gcn_w1    = (const float*)d_in[17];
    const float* gcn_b1    = (const float*)d_in[18];
    const float* gcn_w2    = (const float*)d_in[19];
    const float* gcn_b2    = (const float*)d_in[20];
    const float* m_w1      = (const float*)d_in[21];
    const float* m_b1      = (const float*)d_in[22];
    const float* m_w2      = (const float*)d_in[23];
    const float* m_b2      = (const float*)d_in[24];
    const float* m_w3      = (const float*)d_in[25];
    const float* m_b3      = (const float*)d_in[26];

    float* out_h      = (float*)d_out;                           // [100000,256]
    float* out_losses = (float*)d_out + (size_t)N_TOTAL * H;     // [50000,64]

    cudaMemcpyAsync(out_h, h, (size_t)N_TOTAL * H * sizeof(float),
                    cudaMemcpyDeviceToDevice, 0);

    __nv_bfloat16 *pX1h, *pX1l, *pX2h, *pX2l, *pHgh, *pHgl;
    __nv_bfloat16 *pW1ih_h, *pW1ih_l, *pW2ih_h, *pW2ih_l;
    __nv_bfloat16 *pW1hh_h, *pW1hh_l, *pW2hh_h, *pW2hh_l;
    float *pGI1, *pGH1, *pGI2, *pGH2, *pS, *pHOBS;
    cudaGetSymbolAddress((void**)&pX1h, g_X1h);  cudaGetSymbolAddress((void**)&pX1l, g_X1l);
    cudaGetSymbolAddress((void**)&pX2h, g_X2h);  cudaGetSymbolAddress((void**)&pX2l, g_X2l);
    cudaGetSymbolAddress((void**)&pHgh, g_Hgh);  cudaGetSymbolAddress((void**)&pHgl, g_Hgl);
    cudaGetSymbolAddress((void**)&pW1ih_h, g_W1ih_h); cudaGetSymbolAddress((void**)&pW1ih_l, g_W1ih_l);
    cudaGetSymbolAddress((void**)&pW2ih_h, g_W2ih_h); cudaGetSymbolAddress((void**)&pW2ih_l, g_W2ih_l);
    cudaGetSymbolAddress((void**)&pW1hh_h, g_W1hh_h); cudaGetSymbolAddress((void**)&pW1hh_l, g_W1hh_l);
    cudaGetSymbolAddress((void**)&pW2hh_h, g_W2hh_h); cudaGetSymbolAddress((void**)&pW2hh_l, g_W2hh_l);
    cudaGetSymbolAddress((void**)&pGI1, g_GI1);  cudaGetSymbolAddress((void**)&pGH1, g_GH1);
    cudaGetSymbolAddress((void**)&pGI2, g_GI2);  cudaGetSymbolAddress((void**)&pGH2, g_GH2);
    cudaGetSymbolAddress((void**)&pS, g_S);      cudaGetSymbolAddress((void**)&pHOBS, g_HOBS);

    // GCN: S = f(X@adjT), HOBS = S@adjT + b2
    gcn_gemm<<<(N_OBS + 127) / 128, 256>>>(X_obs, adj, gcn_w1, gcn_b1, gcn_w2, gcn_b2, pS, 0);
    gcn_gemm<<<(N_OBS + 127) / 128, 256>>>(pS,    adj, gcn_w1, gcn_b1, gcn_w2, gcn_b2, pHOBS, 1);

    prep_kernel<<<N_OBS, 256>>>(p_obs, X_obs, M_obs, pHOBS, w_prep, w_prep2, bias_prep,
                                out_losses);

    split_kernel<<<(G3 * XK + 255) / 256, 256>>>(g1_w_ih, pW1ih_h, pW1ih_l, G3 * XK);
    split_kernel<<<(G3 * XK + 255) / 256, 256>>>(g2_w_ih, pW2ih_h, pW2ih_l, G3 * XK);
    split_kernel<<<(G3 * H + 255) / 256, 256>>>(g1_w_hh, pW1hh_h, pW1hh_l, G3 * H);
    split_kernel<<<(G3 * H + 255) / 256, 256>>>(g2_w_hh, pW2hh_h, pW2hh_l, G3 * H);
    gather_split_kernel<<<N_OBS, 256>>>(h, i_obs, pHgh, pHgl);

    cudaFuncSetAttribute(mma_gemm, cudaFuncAttributeMaxDynamicSharedMemorySize, GEMM_SMEM);

    dim3 gg(G3 / 128, (N_OBS + 127) / 128);
    mma_gemm<<<gg, 256, GEMM_SMEM>>>(pX1h, pX1l, pW1ih_h, pW1ih_l, g1_b_ih, pGI1, N_OBS, XK);
    mma_gemm<<<gg, 256, GEMM_SMEM>>>(pHgh, pHgl, pW1hh_h, pW1hh_l, g1_b_hh, pGH1, N_OBS, H);
    mma_gemm<<<gg, 256, GEMM_SMEM>>>(pX2h, pX2l, pW2ih_h, pW2ih_l, g2_b_ih, pGI2, N_OBS, XK);
    mma_gemm<<<gg, 256, GEMM_SMEM>>>(pHgh, pHgl, pW2hh_h, pW2hh_l, g2_b_hh, pGH2, N_OBS, H);

    cudaFuncSetAttribute(gates_mlp_kernel, cudaFuncAttributeMaxDynamicSharedMemorySize, GATES_SMEM);
    gates_mlp_kernel<<<N_OBS / GR, 256, GATES_SMEM>>>(h, i_obs, m_w1, m_b1, m_w2, m_b2,
                                                      m_w3, m_b3, out_h);
}

// round 9
// speedup vs baseline: 4.5286x; 1.2173x over previous
#include <cuda_runtime.h>
#include <cuda_fp16.h>
#include <cstdint>

#define N_OBS   50000
#define N_TOTAL 100000
#define F       64
#define P       16
#define H       256
#define G3      768        // 3*H
#define G6      1536       // fused hh output width
#define XK      1024       // F*P
#define TWO_LOG_LIK_C 1.8378770664093453f

// ---------------- scratch (static __device__ — no allocations) ----------------
__device__ __half g_X1 [(size_t)N_OBS * XK];
__device__ __half g_X2 [(size_t)N_OBS * XK];
__device__ __half g_Hg [(size_t)N_OBS * H];
__device__ __half g_W1ih_h[(size_t)G3 * XK];
__device__ __half g_W1ih_l[(size_t)G3 * XK];
__device__ __half g_W2ih_h[(size_t)G3 * XK];
__device__ __half g_W2ih_l[(size_t)G3 * XK];
__device__ __half g_Whh_h[(size_t)G6 * H];
__device__ __half g_Whh_l[(size_t)G6 * H];
__device__ float g_bhh[G6];
__device__ float g_GI1 [(size_t)N_OBS * G3];
__device__ float g_GI2 [(size_t)N_OBS * G3];
__device__ float g_GH12[(size_t)N_OBS * G6];
__device__ float g_S   [(size_t)N_OBS * F];
__device__ float g_HOBS[(size_t)N_OBS * F];

__device__ __forceinline__ float sigmoidf_(float x) { return 1.0f / (1.0f + expf(-x)); }

__device__ __forceinline__ uint32_t smem_u32(const void* p) {
    uint32_t a;
    asm("{ .reg .u64 t; cvta.to.shared.u64 t, %1; cvt.u32.u64 %0, t; }" : "=r"(a) : "l"(p));
    return a;
}

#define SPLIT_F16(v, hi, lo) do { \
    hi = __float2half(v);         \
    lo = __float2half((v) - __half2float(hi)); } while (0)

// ---------------- GCN as two 64-wide passes over adj ----------------
__global__ void __launch_bounds__(256) gcn_gemm(
    const float* __restrict__ In, const float* __restrict__ adj,
    const float* __restrict__ gw1, const float* __restrict__ gb1,
    const float* __restrict__ gw2, const float* __restrict__ gb2,
    float* __restrict__ Out, int mode)
{
    __shared__ float adj_s[F * 65];
    __shared__ float xrow[4][F];
    const int t = threadIdx.x;
    for (int i = t; i < F * F; i += 256)
        adj_s[(i >> 6) * 65 + (i & 63)] = adj[i];
    __syncthreads();

    const int f  = t & 63;
    const int g4 = t >> 6;
    const int base = blockIdx.x * 128;

    for (int it = 0; it < 32; it++) {
        const int r = base + it * 4 + g4;
        if (r < N_OBS) xrow[g4][f] = In[(size_t)r * F + f];
        __syncthreads();
        if (r < N_OBS) {
            const float* ar = adj_s + f * 65;
            float acc = 0.0f;
            #pragma unroll 16
            for (int g = 0; g < F; g++) acc = fmaf(ar[g], xrow[g4][g], acc);
            if (mode == 0) {
                float s = 0.0f;
                #pragma unroll
                for (int c = 0; c < 32; c++) {
                    float v = fmaf(acc, gw1[c], gb1[c]);
                    s = fmaf(gw2[c], fmaxf(v, 0.0f), s);
                }
                Out[(size_t)r * F + f] = s;
            } else {
                Out[(size_t)r * F + f] = acc + gb2[0];
            }
        }
        __syncthreads();
    }
}

// ---------------- Kernel 1: losses + prep feats (fp16 out) ----------------
__global__ void __launch_bounds__(256) prep_kernel(
    const float* __restrict__ p_obs, const float* __restrict__ X_obs,
    const float* __restrict__ M_obs, const float* __restrict__ hobs_g,
    const float* __restrict__ w_prep, const float* __restrict__ w_prep2,
    const float* __restrict__ bias_prep,
    float* __restrict__ losses_out)
{
    __shared__ float xs[F], means[F], lvs[F], errs[F], ms[F];

    const int n = blockIdx.x;
    const int t = threadIdx.x;

    if (t < F) {
        const int f = t;
        float x    = X_obs[n * F + f];
        float mean = p_obs[n * (2 * F) + f];
        float lv   = p_obs[n * (2 * F) + F + f];
        float m    = M_obs[n * F + f];
        float err  = (x - mean) * expf(-0.5f * lv);
        xs[f] = x; means[f] = mean; lvs[f] = lv; errs[f] = err; ms[f] = m;
        losses_out[n * F + f] = 0.5f * ((err * err + lv + TWO_LOG_LIK_C) * m);
    }
    __syncthreads();

    for (int i = t; i < XK; i += 256) {
        const int f = i >> 4, p = i & 15;
        const float* w = w_prep + f * (4 * P);
        float v = bias_prep[f * P + p];
        v = fmaf(xs[f],    w[p],          v);
        v = fmaf(means[f], w[P + p],      v);
        v = fmaf(lvs[f],   w[2 * P + p],  v);
        v = fmaf(errs[f],  w[3 * P + p],  v);
        v = fmaxf(v, 0.0f) * ms[f];
        g_X1[(size_t)n * XK + i] = __float2half(v);
    }
    for (int i = t; i < XK; i += 256) {
        const int f = i >> 4, p = i & 15;
        const float* w = w_prep2 + f * (5 * P);
        float v = bias_prep[f * P + p];
        v = fmaf(xs[f],             w[p],         v);
        v = fmaf(hobs_g[n * F + f], w[P + p],     v);
        v = fmaf(means[f], w[2 * P + p],  v);
        v = fmaf(lvs[f],   w[3 * P + p],  v);
        v = fmaf(errs[f],  w[4 * P + p],  v);
        v = fmaxf(v, 0.0f) * ms[f];
        g_X2[(size_t)n * XK + i] = __float2half(v);
    }
}

// ---------------- weight split (fp16 hi/lo) and gathers ----------------
__global__ void __launch_bounds__(256) split_kernel(
    const float* __restrict__ src, __half* __restrict__ hi,
    __half* __restrict__ lo, int n)
{
    int i = blockIdx.x * 256 + threadIdx.x;
    if (i < n) {
        float v = src[i];
        __half h, l; SPLIT_F16(v, h, l);
        hi[i] = h; lo[i] = l;
    }
}

__global__ void __launch_bounds__(256) gather_kernel(
    const float* __restrict__ h, const int* __restrict__ i_obs,
    __half* __restrict__ dst)
{
    int n = blockIdx.x, t = threadIdx.x;
    int idx = i_obs[n];
    dst[(size_t)n * H + t] = __float2half(h[(size_t)idx * H + t]);
}

// ---------------- Kernel 2: HMMA fp16 2-term GEMM, 4-stage cp.async ring ----------------
// C[M, Nld] tile slice = A[M,K](fp16) @ (Bh+Bl)[N,K]^T + bias
#define BM 128
#define BN 128
#define BKB 32
#define PITCH 80
#define STAGE_MAT (BM * PITCH)          // 10240 B per matrix
#define STAGE_BYTES (3 * STAGE_MAT)     // A, Bh, Bl = 30720
#define NSTAGE 4
#define GEMM_SMEM (NSTAGE * STAGE_BYTES)  // 122880

__device__ __forceinline__ void cp16(uint32_t dst, const void* src, bool pred) {
    asm volatile("cp.async.cg.shared.global [%0], [%1], 16, %2;"
                 :: "r"(dst), "l"(src), "r"(pred ? 16 : 0));
}
__device__ __forceinline__ void ldm_x4(uint32_t* r, uint32_t addr) {
    asm volatile("ldmatrix.sync.aligned.m8n8.x4.shared.b16 {%0,%1,%2,%3}, [%4];"
                 : "=r"(r[0]), "=r"(r[1]), "=r"(r[2]), "=r"(r[3]) : "r"(addr));
}
__device__ __forceinline__ void mma16816(float* c, const uint32_t* a, uint32_t b0, uint32_t b1) {
    asm volatile("mma.sync.aligned.m16n8k16.row.col.f32.f16.f16.f32 "
                 "{%0,%1,%2,%3}, {%4,%5,%6,%7}, {%8,%9}, {%0,%1,%2,%3};"
                 : "+f"(c[0]), "+f"(c[1]), "+f"(c[2]), "+f"(c[3])
                 : "r"(a[0]), "r"(a[1]), "r"(a[2]), "r"(a[3]), "r"(b0), "r"(b1));
}

__global__ void __launch_bounds__(256, 1) mma_gemm(
    const __half* __restrict__ A,
    const __half* __restrict__ Bh, const __half* __restrict__ Bl,
    const float* __restrict__ bias, float* __restrict__ C,
    int M, int K, int ldc)
{
    extern __shared__ char smem_raw[];
    const uint32_t su = smem_u32(smem_raw);

    const int t    = threadIdx.x;
    const int wid  = t >> 5;
    const int lane = t & 31;
    const int bm   = blockIdx.y * BM;
    const int bn   = blockIdx.x * BN;
    const int nk   = K / BKB;

    const int wm = (wid & 1) * 64;
    const int wn = (wid >> 1) * 32;

    const int rowt  = t >> 2;
    const int chunk = t & 3;

    const int garow0 = bm + rowt, garow1 = bm + rowt + 64;
    const bool p0 = garow0 < M, p1 = garow1 < M;
    const __half* A0  = A  + (size_t)(p0 ? garow0 : 0) * K + chunk * 8;
    const __half* A1  = A  + (size_t)(p1 ? garow1 : 0) * K + chunk * 8;
    const __half* Bh0 = Bh + (size_t)(bn + rowt) * K + chunk * 8;
    const __half* Bh1 = Bh + (size_t)(bn + rowt + 64) * K + chunk * 8;
    const __half* Bl0 = Bl + (size_t)(bn + rowt) * K + chunk * 8;
    const __half* Bl1 = Bl + (size_t)(bn + rowt + 64) * K + chunk * 8;

    const uint32_t d0 = (uint32_t)rowt * PITCH + (uint32_t)chunk * 16;
    const uint32_t d1 = d0 + 64 * PITCH;

    auto load_stage = [&](int kb, int buf) {
        const uint32_t base = su + buf * STAGE_BYTES;
        const int ke = kb * BKB;
        cp16(base + d0,                 A0  + ke, p0);
        cp16(base + d1,                 A1  + ke, p1);
        cp16(base + STAGE_MAT + d0,     Bh0 + ke, true);
        cp16(base + STAGE_MAT + d1,     Bh1 + ke, true);
        cp16(base + 2 * STAGE_MAT + d0, Bl0 + ke, true);
        cp16(base + 2 * STAGE_MAT + d1, Bl1 + ke, true);
        asm volatile("cp.async.commit_group;");
    };

    float acc[4][4][4];
    #pragma unroll
    for (int i = 0; i < 4; i++)
        #pragma unroll
        for (int j = 0; j < 4; j++)
            #pragma unroll
            for (int k = 0; k < 4; k++) acc[i][j][k] = 0.0f;

    load_stage(0, 0);
    load_stage(1, 1);
    load_stage(2, 2);

    int buf = 0;
    for (int kb = 0; kb < nk; kb++) {
        if (kb + 1 < nk) asm volatile("cp.async.wait_group 2;");
        else             asm volatile("cp.async.wait_group 0;");
        __syncthreads();

        const uint32_t sa = su + buf * STAGE_BYTES;
        const uint32_t sb = sa + STAGE_MAT;

        if (kb + 3 < nk) {
            int lbuf = buf + 3; if (lbuf >= NSTAGE) lbuf -= NSTAGE;
            load_stage(kb + 3, lbuf);
        }

        #pragma unroll
        for (int ks = 0; ks < 2; ks++) {
            const uint32_t kbyte = (uint32_t)ks * 32;
            uint32_t a_r[4][4];
            const uint32_t arow = (uint32_t)(wm + (lane & 15)) * PITCH
                                + kbyte + ((uint32_t)(lane >> 4) << 4);
            #pragma unroll
            for (int mf = 0; mf < 4; mf++)
                ldm_x4(a_r[mf], sa + arow + (uint32_t)mf * 16 * PITCH);

            uint32_t b_h[2][4], b_l[2][4];
            const uint32_t brow = (uint32_t)(wn + (((lane >> 3) & 2) << 2) + (lane & 7)) * PITCH
                                + kbyte + (((uint32_t)(lane >> 3) & 1) << 4);
            #pragma unroll
            for (int nfp = 0; nfp < 2; nfp++) {
                uint32_t bd = sb + brow + (uint32_t)nfp * 16 * PITCH;
                ldm_x4(b_h[nfp], bd);
                ldm_x4(b_l[nfp], bd + STAGE_MAT);
            }
            #pragma unroll
            for (int mf = 0; mf < 4; mf++)
                #pragma unroll
                for (int nf = 0; nf < 4; nf++) {
                    const int nfp = nf >> 1, sub = (nf & 1) * 2;
                    mma16816(acc[mf][nf], a_r[mf], b_h[nfp][sub], b_h[nfp][sub + 1]);
                    mma16816(acc[mf][nf], a_r[mf], b_l[nfp][sub], b_l[nfp][sub + 1]);
                }
        }
        buf = buf + 1; if (buf >= NSTAGE) buf -= NSTAGE;
    }

    #pragma unroll
    for (int mf = 0; mf < 4; mf++) {
        const int r0 = bm + wm + mf * 16 + (lane >> 2);
        #pragma unroll
        for (int nf = 0; nf < 4; nf++) {
            const int col = bn + wn + nf * 8 + (lane & 3) * 2;
            const float b0 = bias[col], b1 = bias[col + 1];
            if (r0 < M) {
                float2 v = make_float2(acc[mf][nf][0] + b0, acc[mf][nf][1] + b1);
                *(float2*)(C + (size_t)r0 * ldc + col) = v;
            }
            if (r0 + 8 < M) {
                float2 v = make_float2(acc[mf][nf][2] + b0, acc[mf][nf][3] + b1);
                *(float2*)(C + (size_t)(r0 + 8) * ldc + col) = v;
            }
        }
    }
}

// ---------------- Kernel 3: GRU gates + MLP head (weights cached in smem) ----------------
#define GR 16
#define W1_OFF 0
#define W3_OFF (W1_OFF + 32 * 512)
#define W2_OFF (W3_OFF + 256 * 33)
#define ZIN_OFF (W2_OFF + 32 * 33)
#define Z1_OFF  (ZIN_OFF + 512)
#define Z2_OFF  (Z1_OFF + 32)
#define GATES_SMEM ((Z2_OFF + 32) * 4)

__global__ void __launch_bounds__(256) gates_mlp_kernel(
    const float* __restrict__ h, const int* __restrict__ i_obs,
    const float* __restrict__ m_w1, const float* __restrict__ m_b1,
    const float* __restrict__ m_w2, const float* __restrict__ m_b2,
    const float* __restrict__ m_w3, const float* __restrict__ m_b3,
    float* __restrict__ out_h)
{
    extern __shared__ float sm[];
    float* w1s = sm + W1_OFF;
    float* w3s = sm + W3_OFF;
    float* w2s = sm + W2_OFF;
    float* zin = sm + ZIN_OFF;
    float* z1  = sm + Z1_OFF;
    float* z2  = sm + Z2_OFF;

    const int t    = threadIdx.x;
    const int wid  = t >> 5;
    const int lane = t & 31;

    for (int i = t; i < 32 * 512; i += 256) w1s[i] = m_w1[i];
    for (int i = t; i < 256 * 32; i += 256) w3s[(i >> 5) * 33 + (i & 31)] = m_w3[i];
    for (int i = t; i < 32 * 32;  i += 256) w2s[(i >> 5) * 33 + (i & 31)] = m_w2[i];
    __syncthreads();

    const int n0 = blockIdx.x * GR;
    for (int r = 0; r < GR; r++) {
        const int n = n0 + r;
        const int idx = i_obs[n];
        const size_t b  = (size_t)n * G3;
        const size_t bh = (size_t)n * G6;

        const float hg = h[(size_t)idx * H + t];
        {
            float rr = sigmoidf_(g_GI1[b + t]       + g_GH12[bh + t]);
            float zz = sigmoidf_(g_GI1[b + H + t]   + g_GH12[bh + H + t]);
            float ng = tanhf(g_GI1[b + 2 * H + t] + rr * g_GH12[bh + 2 * H + t]);
            zin[t] = (1.0f - zz) * ng + zz * hg;
        }
        {
            float rr = sigmoidf_(g_GI2[b + t]       + g_GH12[bh + G3 + t]);
            float zz = sigmoidf_(g_GI2[b + H + t]   + g_GH12[bh + G3 + H + t]);
            float ng = tanhf(g_GI2[b + 2 * H + t] + rr * g_GH12[bh + G3 + 2 * H + t]);
            zin[H + t] = (1.0f - zz) * ng + zz * hg;
        }
        __syncthreads();

        #pragma unroll
        for (int q = 0; q < 4; q++) {
            const int o = 4 * wid + q;
            const float* wrow = w1s + o * 512;
            float s = 0.0f;
            #pragma unroll
            for (int j = 0; j < 16; j++)
                s = fmaf(zin[lane + 32 * j], wrow[lane + 32 * j], s);
            #pragma unroll
            for (int off = 16; off > 0; off >>= 1)
                s += __shfl_xor_sync(0xFFFFFFFFu, s, off);
            if (lane == 0) z1[o] = fmaxf(s + m_b1[o], 0.0f);
        }
        __syncthreads();

        if (t < 32) {
            const float* w = w2s + t * 33;
            float s = m_b2[t];
            #pragma unroll
            for (int k = 0; k < 32; k++) s = fmaf(z1[k], w[k], s);
            z2[t] = fmaxf(s, 0.0f);
        }
        __syncthreads();

        {
            const float* w = w3s + t * 33;
            float s = m_b3[t];
            #pragma unroll
            for (int k = 0; k < 32; k++) s = fmaf(z2[k], w[k], s);
            out_h[(size_t)idx * H + t] = s * sigmoidf_(s);
        }
        __syncthreads();
    }
}

// ---------------- launch ----------------
extern "C" void kernel_launch(void* const* d_in, const int* in_sizes, int n_in,
                              void* d_out, int out_size)
{
    const float* h         = (const float*)d_in[0];
    const float* p_obs     = (const float*)d_in[1];
    const float* X_obs     = (const float*)d_in[2];
    const float* M_obs     = (const float*)d_in[3];
    const float* adj       = (const float*)d_in[4];
    const int*   i_obs     = (const int*)  d_in[5];
    const float* w_prep    = (const float*)d_in[6];
    const float* w_prep2   = (const float*)d_in[7];
    const float* bias_prep = (const float*)d_in[8];
    const float* g1_w_ih   = (const float*)d_in[9];
    const float* g1_w_hh   = (const float*)d_in[10];
    const float* g1_b_ih   = (const float*)d_in[11];
    const float* g1_b_hh   = (const float*)d_in[12];
    const float* g2_w_ih   = (const float*)d_in[13];
    const float* g2_w_hh   = (const float*)d_in[14];
    const float* g2_b_ih   = (const float*)d_in[15];
    const float* g2_b_hh   = (const float*)d_in[16];
    const float* gcn_w1    = (const float*)d_in[17];
    const float* gcn_b1    = (const float*)d_in[18];
    const float* gcn_w2    = (const float*)d_in[19];
    const float* gcn_b2    = (const float*)d_in[20];
    const float* m_w1      = (const float*)d_in[21];
    const float* m_b1      = (const float*)d_in[22];
    const float* m_w2      = (const float*)d_in[23];
    const float* m_b2      = (const float*)d_in[24];
    const float* m_w3      = (const float*)d_in[25];
    const float* m_b3      = (const float*)d_in[26];

    float* out_h      = (float*)d_out;                           // [100000,256]
    float* out_losses = (float*)d_out + (size_t)N_TOTAL * H;     // [50000,64]

    cudaMemcpyAsync(out_h, h, (size_t)N_TOTAL * H * sizeof(float),
                    cudaMemcpyDeviceToDevice, 0);

    __half *pX1, *pX2, *pHg;
    __half *pW1ih_h, *pW1ih_l, *pW2ih_h, *pW2ih_l, *pWhh_h, *pWhh_l;
    float *pGI1, *pGI2, *pGH12, *pS, *pHOBS, *pbhh;
    cudaGetSymbolAddress((void**)&pX1, g_X1);
    cudaGetSymbolAddress((void**)&pX2, g_X2);
    cudaGetSymbolAddress((void**)&pHg, g_Hg);
    cudaGetSymbolAddress((void**)&pW1ih_h, g_W1ih_h); cudaGetSymbolAddress((void**)&pW1ih_l, g_W1ih_l);
    cudaGetSymbolAddress((void**)&pW2ih_h, g_W2ih_h); cudaGetSymbolAddress((void**)&pW2ih_l, g_W2ih_l);
    cudaGetSymbolAddress((void**)&pWhh_h, g_Whh_h);   cudaGetSymbolAddress((void**)&pWhh_l, g_Whh_l);
    cudaGetSymbolAddress((void**)&pGI1, g_GI1);
    cudaGetSymbolAddress((void**)&pGI2, g_GI2);
    cudaGetSymbolAddress((void**)&pGH12, g_GH12);
    cudaGetSymbolAddress((void**)&pS, g_S);
    cudaGetSymbolAddress((void**)&pHOBS, g_HOBS);
    cudaGetSymbolAddress((void**)&pbhh, g_bhh);

    // fused hh bias
    cudaMemcpyAsync(pbhh,      g1_b_hh, G3 * sizeof(float), cudaMemcpyDeviceToDevice, 0);
    cudaMemcpyAsync(pbhh + G3, g2_b_hh, G3 * sizeof(float), cudaMemcpyDeviceToDevice, 0);

    // GCN: S = f(X@adjT), HOBS = S@adjT + b2
    gcn_gemm<<<(N_OBS + 127) / 128, 256>>>(X_obs, adj, gcn_w1, gcn_b1, gcn_w2, gcn_b2, pS, 0);
    gcn_gemm<<<(N_OBS + 127) / 128, 256>>>(pS,    adj, gcn_w1, gcn_b1, gcn_w2, gcn_b2, pHOBS, 1);

    prep_kernel<<<N_OBS, 256>>>(p_obs, X_obs, M_obs, pHOBS, w_prep, w_prep2, bias_prep,
                                out_losses);

    split_kernel<<<(G3 * XK + 255) / 256, 256>>>(g1_w_ih, pW1ih_h, pW1ih_l, G3 * XK);
    split_kernel<<<(G3 * XK + 255) / 256, 256>>>(g2_w_ih, pW2ih_h, pW2ih_l, G3 * XK);
    split_kernel<<<(G3 * H + 255) / 256, 256>>>(g1_w_hh, pWhh_h,            pWhh_l,            G3 * H);
    split_kernel<<<(G3 * H + 255) / 256, 256>>>(g2_w_hh, pWhh_h + (size_t)G3 * H, pWhh_l + (size_t)G3 * H, G3 * H);
    gather_kernel<<<N_OBS, 256>>>(h, i_obs, pHg);

    cudaFuncSetAttribute(mma_gemm, cudaFuncAttributeMaxDynamicSharedMemorySize, GEMM_SMEM);

    dim3 gg_ih(G3 / 128, (N_OBS + 127) / 128);
    dim3 gg_hh(G6 / 128, (N_OBS + 127) / 128);
    mma_gemm<<<gg_ih, 256, GEMM_SMEM>>>(pX1, pW1ih_h, pW1ih_l, g1_b_ih, pGI1, N_OBS, XK, G3);
    mma_gemm<<<gg_ih, 256, GEMM_SMEM>>>(pX2, pW2ih_h, pW2ih_l, g2_b_ih, pGI2, N_OBS, XK, G3);
    mma_gemm<<<gg_hh, 256, GEMM_SMEM>>>(pHg, pWhh_h,  pWhh_l,  pbhh,    pGH12, N_OBS, H, G6);

    cudaFuncSetAttribute(gates_mlp_kernel, cudaFuncAttributeMaxDynamicSharedMemorySize, GATES_SMEM);
    gates_mlp_kernel<<<N_OBS / GR, 256, GATES_SMEM>>>(h, i_obs, m_w1, m_b1, m_w2, m_b2,
                                                      m_w3, m_b3, out_h);
}

// round 10
// speedup vs baseline: 5.4810x; 1.2103x over previous
#include <cuda_runtime.h>
#include <cuda_fp16.h>
#include <cstdint>

#define N_OBS   50000
#define N_TOTAL 100000
#define F       64
#define P       16
#define H       256
#define G3      768        // 3*H
#define G6      1536       // fused hh output width
#define XK      1024       // F*P
#define TWO_LOG_LIK_C 1.8378770664093453f

// ---------------- scratch (static __device__ — no allocations) ----------------
__device__ __half g_X1 [(size_t)N_OBS * XK];
__device__ __half g_X2 [(size_t)N_OBS * XK];
__device__ __half g_Hg [(size_t)N_OBS * H];
__device__ __half g_W1ih[(size_t)G3 * XK];
__device__ __half g_W2ih[(size_t)G3 * XK];
__device__ __half g_Whh [(size_t)G6 * H];
__device__ float g_bhh[G6];
__device__ float g_GI1 [(size_t)N_OBS * G3];
__device__ float g_GI2 [(size_t)N_OBS * G3];
__device__ float g_GH12[(size_t)N_OBS * G6];
__device__ float g_S   [(size_t)N_OBS * F];
__device__ float g_HOBS[(size_t)N_OBS * F];

__device__ __forceinline__ float sigmoidf_(float x) { return 1.0f / (1.0f + expf(-x)); }

__device__ __forceinline__ uint32_t smem_u32(const void* p) {
    uint32_t a;
    asm("{ .reg .u64 t; cvta.to.shared.u64 t, %1; cvt.u32.u64 %0, t; }" : "=r"(a) : "l"(p));
    return a;
}

// ---------------- GCN as two 64-wide passes over adj ----------------
__global__ void __launch_bounds__(256) gcn_gemm(
    const float* __restrict__ In, const float* __restrict__ adj,
    const float* __restrict__ gw1, const float* __restrict__ gb1,
    const float* __restrict__ gw2, const float* __restrict__ gb2,
    float* __restrict__ Out, int mode)
{
    __shared__ float adj_s[F * 65];
    __shared__ float xrow[4][F];
    const int t = threadIdx.x;
    for (int i = t; i < F * F; i += 256)
        adj_s[(i >> 6) * 65 + (i & 63)] = adj[i];
    __syncthreads();

    const int f  = t & 63;
    const int g4 = t >> 6;
    const int base = blockIdx.x * 128;

    for (int it = 0; it < 32; it++) {
        const int r = base + it * 4 + g4;
        if (r < N_OBS) xrow[g4][f] = In[(size_t)r * F + f];
        __syncthreads();
        if (r < N_OBS) {
            const float* ar = adj_s + f * 65;
            float acc = 0.0f;
            #pragma unroll 16
            for (int g = 0; g < F; g++) acc = fmaf(ar[g], xrow[g4][g], acc);
            if (mode == 0) {
                float s = 0.0f;
                #pragma unroll
                for (int c = 0; c < 32; c++) {
                    float v = fmaf(acc, gw1[c], gb1[c]);
                    s = fmaf(gw2[c], fmaxf(v, 0.0f), s);
                }
                Out[(size_t)r * F + f] = s;
            } else {
                Out[(size_t)r * F + f] = acc + gb2[0];
            }
        }
        __syncthreads();
    }
}

// ---------------- Kernel 1: losses + prep feats (fp16 out), 16 rows/block ----------------
#define PREP_ROWS 16
__global__ void __launch_bounds__(256) prep_kernel(
    const float* __restrict__ p_obs, const float* __restrict__ X_obs,
    const float* __restrict__ M_obs, const float* __restrict__ hobs_g,
    const float* __restrict__ w_prep, const float* __restrict__ w_prep2,
    const float* __restrict__ bias_prep,
    float* __restrict__ losses_out)
{
    __shared__ float wp1[F * 4 * P];    // 16 KB
    __shared__ float wp2[F * 5 * P];    // 20 KB
    __shared__ float bp [F * P];        // 4 KB
    __shared__ float xs[F], means[F], lvs[F], errs[F], ms[F], hob[F];

    const int t = threadIdx.x;

    for (int i = t; i < F * 4 * P; i += 256) wp1[i] = w_prep[i];
    for (int i = t; i < F * 5 * P; i += 256) wp2[i] = w_prep2[i];
    for (int i = t; i < F * P;     i += 256) bp[i]  = bias_prep[i];
    __syncthreads();

    const int n0 = blockIdx.x * PREP_ROWS;
    for (int r = 0; r < PREP_ROWS; r++) {
        const int n = n0 + r;
        if (t < F) {
            const int f = t;
            float x    = X_obs[n * F + f];
            float mean = p_obs[n * (2 * F) + f];
            float lv   = p_obs[n * (2 * F) + F + f];
            float m    = M_obs[n * F + f];
            float err  = (x - mean) * expf(-0.5f * lv);
            xs[f] = x; means[f] = mean; lvs[f] = lv; errs[f] = err; ms[f] = m;
            hob[f] = hobs_g[n * F + f];
            losses_out[n * F + f] = 0.5f * ((err * err + lv + TWO_LOG_LIK_C) * m);
        }
        __syncthreads();

        #pragma unroll
        for (int rep = 0; rep < 4; rep++) {
            const int i = t + rep * 256;
            const int f = i >> 4, p = i & 15;
            const float* w1 = wp1 + f * (4 * P);
            float v1 = bp[f * P + p];
            v1 = fmaf(xs[f],    w1[p],          v1);
            v1 = fmaf(means[f], w1[P + p],      v1);
            v1 = fmaf(lvs[f],   w1[2 * P + p],  v1);
            v1 = fmaf(errs[f],  w1[3 * P + p],  v1);
            g_X1[(size_t)n * XK + i] = __float2half(fmaxf(v1, 0.0f) * ms[f]);

            const float* w2 = wp2 + f * (5 * P);
            float v2 = bp[f * P + p];
            v2 = fmaf(xs[f],    w2[p],          v2);
            v2 = fmaf(hob[f],   w2[P + p],      v2);
            v2 = fmaf(means[f], w2[2 * P + p],  v2);
            v2 = fmaf(lvs[f],   w2[3 * P + p],  v2);
            v2 = fmaf(errs[f],  w2[4 * P + p],  v2);
            g_X2[(size_t)n * XK + i] = __float2half(fmaxf(v2, 0.0f) * ms[f]);
        }
        __syncthreads();
    }
}

// ---------------- fp32 -> fp16 convert and gather ----------------
__global__ void __launch_bounds__(256) convert_kernel(
    const float* __restrict__ src, __half* __restrict__ dst, int n)
{
    int i = blockIdx.x * 256 + threadIdx.x;
    if (i < n) dst[i] = __float2half(src[i]);
}

__global__ void __launch_bounds__(256) gather_kernel(
    const float* __restrict__ h, const int* __restrict__ i_obs,
    __half* __restrict__ dst)
{
    int n = blockIdx.x, t = threadIdx.x;
    int idx = i_obs[n];
    dst[(size_t)n * H + t] = __float2half(h[(size_t)idx * H + t]);
}

// ---------------- Kernel 2: HMMA fp16 single-term GEMM, 5-stage cp.async ring ----------------
#define BM 128
#define BN 128
#define BKB 32
#define PITCH 80
#define STAGE_MAT (BM * PITCH)          // 10240 B per matrix
#define STAGE_BYTES (2 * STAGE_MAT)     // A, B = 20480
#define NSTAGE 5
#define GEMM_SMEM (NSTAGE * STAGE_BYTES)  // 102400

__device__ __forceinline__ void cp16(uint32_t dst, const void* src, bool pred) {
    asm volatile("cp.async.cg.shared.global [%0], [%1], 16, %2;"
                 :: "r"(dst), "l"(src), "r"(pred ? 16 : 0));
}
__device__ __forceinline__ void ldm_x4(uint32_t* r, uint32_t addr) {
    asm volatile("ldmatrix.sync.aligned.m8n8.x4.shared.b16 {%0,%1,%2,%3}, [%4];"
                 : "=r"(r[0]), "=r"(r[1]), "=r"(r[2]), "=r"(r[3]) : "r"(addr));
}
__device__ __forceinline__ void mma16816(float* c, const uint32_t* a, uint32_t b0, uint32_t b1) {
    asm volatile("mma.sync.aligned.m16n8k16.row.col.f32.f16.f16.f32 "
                 "{%0,%1,%2,%3}, {%4,%5,%6,%7}, {%8,%9}, {%0,%1,%2,%3};"
                 : "+f"(c[0]), "+f"(c[1]), "+f"(c[2]), "+f"(c[3])
                 : "r"(a[0]), "r"(a[1]), "r"(a[2]), "r"(a[3]), "r"(b0), "r"(b1));
}

__global__ void __launch_bounds__(256, 1) mma_gemm(
    const __half* __restrict__ A, const __half* __restrict__ B,
    const float* __restrict__ bias, float* __restrict__ C,
    int M, int K, int ldc)
{
    extern __shared__ char smem_raw[];
    const uint32_t su = smem_u32(smem_raw);

    const int t    = threadIdx.x;
    const int wid  = t >> 5;
    const int lane = t & 31;
    const int bm   = blockIdx.y * BM;
    const int bn   = blockIdx.x * BN;
    const int nk   = K / BKB;

    const int wm = (wid & 1) * 64;
    const int wn = (wid >> 1) * 32;

    const int rowt  = t >> 2;
    const int chunk = t & 3;

    const int garow0 = bm + rowt, garow1 = bm + rowt + 64;
    const bool p0 = garow0 < M, p1 = garow1 < M;
    const __half* A0 = A + (size_t)(p0 ? garow0 : 0) * K + chunk * 8;
    const __half* A1 = A + (size_t)(p1 ? garow1 : 0) * K + chunk * 8;
    const __half* B0 = B + (size_t)(bn + rowt) * K + chunk * 8;
    const __half* B1 = B + (size_t)(bn + rowt + 64) * K + chunk * 8;

    const uint32_t d0 = (uint32_t)rowt * PITCH + (uint32_t)chunk * 16;
    const uint32_t d1 = d0 + 64 * PITCH;

    auto load_stage = [&](int kb, int buf) {
        const uint32_t base = su + buf * STAGE_BYTES;
        const int ke = kb * BKB;
        cp16(base + d0,             A0 + ke, p0);
        cp16(base + d1,             A1 + ke, p1);
        cp16(base + STAGE_MAT + d0, B0 + ke, true);
        cp16(base + STAGE_MAT + d1, B1 + ke, true);
        asm volatile("cp.async.commit_group;");
    };

    float acc[4][4][4];
    #pragma unroll
    for (int i = 0; i < 4; i++)
        #pragma unroll
        for (int j = 0; j < 4; j++)
            #pragma unroll
            for (int k = 0; k < 4; k++) acc[i][j][k] = 0.0f;

    load_stage(0, 0);
    load_stage(1, 1);
    load_stage(2, 2);
    load_stage(3, 3);

    int buf = 0;
    for (int kb = 0; kb < nk; kb++) {
        asm volatile("cp.async.wait_group 3;");
        __syncthreads();

        const uint32_t sa = su + buf * STAGE_BYTES;
        const uint32_t sb = sa + STAGE_MAT;

        if (kb + 4 < nk) {
            int lbuf = buf + 4; if (lbuf >= NSTAGE) lbuf -= NSTAGE;
            load_stage(kb + 4, lbuf);
        }

        #pragma unroll
        for (int ks = 0; ks < 2; ks++) {
            const uint32_t kbyte = (uint32_t)ks * 32;
            uint32_t a_r[4][4];
            const uint32_t arow = (uint32_t)(wm + (lane & 15)) * PITCH
                                + kbyte + ((uint32_t)(lane >> 4) << 4);
            #pragma unroll
            for (int mf = 0; mf < 4; mf++)
                ldm_x4(a_r[mf], sa + arow + (uint32_t)mf * 16 * PITCH);

            uint32_t b_r[2][4];
            const uint32_t brow = (uint32_t)(wn + (((lane >> 3) & 2) << 2) + (lane & 7)) * PITCH
                                + kbyte + (((uint32_t)(lane >> 3) & 1) << 4);
            #pragma unroll
            for (int nfp = 0; nfp < 2; nfp++)
                ldm_x4(b_r[nfp], sb + brow + (uint32_t)nfp * 16 * PITCH);

            #pragma unroll
            for (int mf = 0; mf < 4; mf++)
                #pragma unroll
                for (int nf = 0; nf < 4; nf++) {
                    const int nfp = nf >> 1, sub = (nf & 1) * 2;
                    mma16816(acc[mf][nf], a_r[mf], b_r[nfp][sub], b_r[nfp][sub + 1]);
                }
        }
        buf = buf + 1; if (buf >= NSTAGE) buf -= NSTAGE;
    }

    #pragma unroll
    for (int mf = 0; mf < 4; mf++) {
        const int r0 = bm + wm + mf * 16 + (lane >> 2);
        #pragma unroll
        for (int nf = 0; nf < 4; nf++) {
            const int col = bn + wn + nf * 8 + (lane & 3) * 2;
            const float b0 = bias[col], b1 = bias[col + 1];
            if (r0 < M) {
                float2 v = make_float2(acc[mf][nf][0] + b0, acc[mf][nf][1] + b1);
                *(float2*)(C + (size_t)r0 * ldc + col) = v;
            }
            if (r0 + 8 < M) {
                float2 v = make_float2(acc[mf][nf][2] + b0, acc[mf][nf][3] + b1);
                *(float2*)(C + (size_t)(r0 + 8) * ldc + col) = v;
            }
        }
    }
}

// ---------------- Kernel 3: GRU gates + MLP head (weights cached in smem) ----------------
#define GR 16
#define W1_OFF 0
#define W3_OFF (W1_OFF + 32 * 512)
#define W2_OFF (W3_OFF + 256 * 33)
#define ZIN_OFF (W2_OFF + 32 * 33)
#define Z1_OFF  (ZIN_OFF + 512)
#define Z2_OFF  (Z1_OFF + 32)
#define GATES_SMEM ((Z2_OFF + 32) * 4)

__global__ void __launch_bounds__(256) gates_mlp_kernel(
    const float* __restrict__ h, const int* __restrict__ i_obs,
    const float* __restrict__ m_w1, const float* __restrict__ m_b1,
    const float* __restrict__ m_w2, const float* __restrict__ m_b2,
    const float* __restrict__ m_w3, const float* __restrict__ m_b3,
    float* __restrict__ out_h)
{
    extern __shared__ float sm[];
    float* w1s = sm + W1_OFF;
    float* w3s = sm + W3_OFF;
    float* w2s = sm + W2_OFF;
    float* zin = sm + ZIN_OFF;
    float* z1  = sm + Z1_OFF;
    float* z2  = sm + Z2_OFF;

    const int t    = threadIdx.x;
    const int wid  = t >> 5;
    const int lane = t & 31;

    for (int i = t; i < 32 * 512; i += 256) w1s[i] = m_w1[i];
    for (int i = t; i < 256 * 32; i += 256) w3s[(i >> 5) * 33 + (i & 31)] = m_w3[i];
    for (int i = t; i < 32 * 32;  i += 256) w2s[(i >> 5) * 33 + (i & 31)] = m_w2[i];
    __syncthreads();

    const int n0 = blockIdx.x * GR;
    for (int r = 0; r < GR; r++) {
        const int n = n0 + r;
        const int idx = i_obs[n];
        const size_t b  = (size_t)n * G3;
        const size_t bh = (size_t)n * G6;

        const float hg = h[(size_t)idx * H + t];
        {
            float rr = sigmoidf_(g_GI1[b + t]       + g_GH12[bh + t]);
            float zz = sigmoidf_(g_GI1[b + H + t]   + g_GH12[bh + H + t]);
            float ng = tanhf(g_GI1[b + 2 * H + t] + rr * g_GH12[bh + 2 * H + t]);
            zin[t] = (1.0f - zz) * ng + zz * hg;
        }
        {
            float rr = sigmoidf_(g_GI2[b + t]       + g_GH12[bh + G3 + t]);
            float zz = sigmoidf_(g_GI2[b + H + t]   + g_GH12[bh + G3 + H + t]);
            float ng = tanhf(g_GI2[b + 2 * H + t] + rr * g_GH12[bh + G3 + 2 * H + t]);
            zin[H + t] = (1.0f - zz) * ng + zz * hg;
        }
        __syncthreads();

        #pragma unroll
        for (int q = 0; q < 4; q++) {
            const int o = 4 * wid + q;
            const float* wrow = w1s + o * 512;
            float s = 0.0f;
            #pragma unroll
            for (int j = 0; j < 16; j++)
                s = fmaf(zin[lane + 32 * j], wrow[lane + 32 * j], s);
            #pragma unroll
            for (int off = 16; off > 0; off >>= 1)
                s += __shfl_xor_sync(0xFFFFFFFFu, s, off);
            if (lane == 0) z1[o] = fmaxf(s + m_b1[o], 0.0f);
        }
        __syncthreads();

        if (t < 32) {
            const float* w = w2s + t * 33;
            float s = m_b2[t];
            #pragma unroll
            for (int k = 0; k < 32; k++) s = fmaf(z1[k], w[k], s);
            z2[t] = fmaxf(s, 0.0f);
        }
        __syncthreads();

        {
            const float* w = w3s + t * 33;
            float s = m_b3[t];
            #pragma unroll
            for (int k = 0; k < 32; k++) s = fmaf(z2[k], w[k], s);
            out_h[(size_t)idx * H + t] = s * sigmoidf_(s);
        }
        __syncthreads();
    }
}

// ---------------- launch ----------------
extern "C" void kernel_launch(void* const* d_in, const int* in_sizes, int n_in,
                              void* d_out, int out_size)
{
    const float* h         = (const float*)d_in[0];
    const float* p_obs     = (const float*)d_in[1];
    const float* X_obs     = (const float*)d_in[2];
    const float* M_obs     = (const float*)d_in[3];
    const float* adj       = (const float*)d_in[4];
    const int*   i_obs     = (const int*)  d_in[5];
    const float* w_prep    = (const float*)d_in[6];
    const float* w_prep2   = (const float*)d_in[7];
    const float* bias_prep = (const float*)d_in[8];
    const float* g1_w_ih   = (const float*)d_in[9];
    const float* g1_w_hh   = (const float*)d_in[10];
    const float* g1_b_ih   = (const float*)d_in[11];
    const float* g1_b_hh   = (const float*)d_in[12];
    const float* g2_w_ih   = (const float*)d_in[13];
    const float* g2_w_hh   = (const float*)d_in[14];
    const float* g2_b_ih   = (const float*)d_in[15];
    const float* g2_b_hh   = (const float*)d_in[16];
    const float* gcn_w1    = (const float*)d_in[17];
    const float* gcn_b1    = (const float*)d_in[18];
    const float* gcn_w2    = (const float*)d_in[19];
    const float* gcn_b2    = (const float*)d_in[20];
    const float* m_w1      = (const float*)d_in[21];
    const float* m_b1      = (const float*)d_in[22];
    const float* m_w2      = (const float*)d_in[23];
    const float* m_b2      = (const float*)d_in[24];
    const float* m_w3      = (const float*)d_in[25];
    const float* m_b3      = (const float*)d_in[26];

    float* out_h      = (float*)d_out;                           // [100000,256]
    float* out_losses = (float*)d_out + (size_t)N_TOTAL * H;     // [50000,64]

    cudaMemcpyAsync(out_h, h, (size_t)N_TOTAL * H * sizeof(float),
                    cudaMemcpyDeviceToDevice, 0);

    __half *pX1, *pX2, *pHg, *pW1ih, *pW2ih, *pWhh;
    float *pGI1, *pGI2, *pGH12, *pS, *pHOBS, *pbhh;
    cudaGetSymbolAddress((void**)&pX1, g_X1);
    cudaGetSymbolAddress((void**)&pX2, g_X2);
    cudaGetSymbolAddress((void**)&pHg, g_Hg);
    cudaGetSymbolAddress((void**)&pW1ih, g_W1ih);
    cudaGetSymbolAddress((void**)&pW2ih, g_W2ih);
    cudaGetSymbolAddress((void**)&pWhh, g_Whh);
    cudaGetSymbolAddress((void**)&pGI1, g_GI1);
    cudaGetSymbolAddress((void**)&pGI2, g_GI2);
    cudaGetSymbolAddress((void**)&pGH12, g_GH12);
    cudaGetSymbolAddress((void**)&pS, g_S);
    cudaGetSymbolAddress((void**)&pHOBS, g_HOBS);
    cudaGetSymbolAddress((void**)&pbhh, g_bhh);

    // fused hh bias
    cudaMemcpyAsync(pbhh,      g1_b_hh, G3 * sizeof(float), cudaMemcpyDeviceToDevice, 0);
    cudaMemcpyAsync(pbhh + G3, g2_b_hh, G3 * sizeof(float), cudaMemcpyDeviceToDevice, 0);

    // GCN: S = f(X@adjT), HOBS = S@adjT + b2
    gcn_gemm<<<(N_OBS + 127) / 128, 256>>>(X_obs, adj, gcn_w1, gcn_b1, gcn_w2, gcn_b2, pS, 0);
    gcn_gemm<<<(N_OBS + 127) / 128, 256>>>(pS,    adj, gcn_w1, gcn_b1, gcn_w2, gcn_b2, pHOBS, 1);

    prep_kernel<<<N_OBS / PREP_ROWS, 256>>>(p_obs, X_obs, M_obs, pHOBS,
                                            w_prep, w_prep2, bias_prep, out_losses);

    convert_kernel<<<(G3 * XK + 255) / 256, 256>>>(g1_w_ih, pW1ih, G3 * XK);
    convert_kernel<<<(G3 * XK + 255) / 256, 256>>>(g2_w_ih, pW2ih, G3 * XK);
    convert_kernel<<<(G3 * H + 255) / 256, 256>>>(g1_w_hh, pWhh, G3 * H);
    convert_kernel<<<(G3 * H + 255) / 256, 256>>>(g2_w_hh, pWhh + (size_t)G3 * H, G3 * H);
    gather_kernel<<<N_OBS, 256>>>(h, i_obs, pHg);

    cudaFuncSetAttribute(mma_gemm, cudaFuncAttributeMaxDynamicSharedMemorySize, GEMM_SMEM);

    dim3 gg_ih(G3 / 128, (N_OBS + 127) / 128);
    dim3 gg_hh(G6 / 128, (N_OBS + 127) / 128);
    mma_gemm<<<gg_ih, 256, GEMM_SMEM>>>(pX1, pW1ih, g1_b_ih, pGI1, N_OBS, XK, G3);
    mma_gemm<<<gg_ih, 256, GEMM_SMEM>>>(pX2, pW2ih, g2_b_ih, pGI2, N_OBS, XK, G3);
    mma_gemm<<<gg_hh, 256, GEMM_SMEM>>>(pHg, pWhh,  pbhh,    pGH12, N_OBS, H, G6);

    cudaFuncSetAttribute(gates_mlp_kernel, cudaFuncAttributeMaxDynamicSharedMemorySize, GATES_SMEM);
    gates_mlp_kernel<<<N_OBS / GR, 256, GATES_SMEM>>>(h, i_obs, m_w1, m_b1, m_w2, m_b2,
                                                      m_w3, m_b3, out_h);
}

// round 13
// speedup vs baseline: 5.9218x; 1.0804x over previous
#include <cuda_runtime.h>
#include <cuda_fp16.h>
#include <cstdint>

#define N_OBS   50000
#define N_TOTAL 100000
#define F       64
#define P       16
#define H       256
#define G3      768        // 3*H
#define G6      1536       // fused hh output width
#define XK      1024       // F*P
#define TWO_LOG_LIK_C 1.8378770664093453f

// ---------------- scratch (static __device__ — no allocations) ----------------
__device__ __half g_X1 [(size_t)N_OBS * XK];
__device__ __half g_X2 [(size_t)N_OBS * XK];
__device__ __half g_Hg [(size_t)N_OBS * H];
__device__ __half g_W1ih[(size_t)G3 * XK];
__device__ __half g_W2ih[(size_t)G3 * XK];
__device__ __half g_Whh [(size_t)G6 * H];
__device__ float g_bhh[G6];
__device__ __half g_GI1 [(size_t)N_OBS * G3];
__device__ __half g_GI2 [(size_t)N_OBS * G3];
__device__ __half g_GH12[(size_t)N_OBS * G6];

__device__ __forceinline__ float sigmoidf_(float x) {
    return __fdividef(1.0f, 1.0f + __expf(-x));
}

__device__ __forceinline__ uint32_t smem_u32(const void* p) {
    uint32_t a;
    asm("{ .reg .u64 t; cvta.to.shared.u64 t, %1; cvt.u32.u64 %0, t; }" : "=r"(a) : "l"(p));
    return a;
}

// ---------------- Kernel 1: losses + fused GCN + prep feats (fp16 out) ----------------
// dynamic smem layout (floats)
#define PR_WP1  0                      // 4096
#define PR_WP2  (PR_WP1 + F * 4 * P)   // 5120
#define PR_BP   (PR_WP2 + F * 5 * P)   // 1024
#define PR_ADJ  (PR_BP + F * P)        // 64*65 = 4160
#define PR_XS   (PR_ADJ + F * 65)
#define PR_MEAN (PR_XS + F)
#define PR_LV   (PR_MEAN + F)
#define PR_ERR  (PR_LV + F)
#define PR_MS   (PR_ERR + F)
#define PR_HOB  (PR_MS + F)
#define PR_AXS  (PR_HOB + F)
#define PR_SS   (PR_AXS + F)
#define PREP_SMEM ((PR_SS + F) * 4)
#define PREP_ROWS 16

__global__ void __launch_bounds__(256) prep_kernel(
    const float* __restrict__ p_obs, const float* __restrict__ X_obs,
    const float* __restrict__ M_obs, const float* __restrict__ adj,
    const float* __restrict__ w_prep, const float* __restrict__ w_prep2,
    const float* __restrict__ bias_prep,
    const float* __restrict__ gw1, const float* __restrict__ gb1,
    const float* __restrict__ gw2, const float* __restrict__ gb2,
    float* __restrict__ losses_out)
{
    extern __shared__ float sp[];
    float* wp1   = sp + PR_WP1;
    float* wp2   = sp + PR_WP2;
    float* bp    = sp + PR_BP;
    float* adj_s = sp + PR_ADJ;
    float* xs    = sp + PR_XS;
    float* means = sp + PR_MEAN;
    float* lvs   = sp + PR_LV;
    float* errs  = sp + PR_ERR;
    float* ms    = sp + PR_MS;
    float* hob   = sp + PR_HOB;
    float* axs   = sp + PR_AXS;
    float* ss    = sp + PR_SS;

    const int t = threadIdx.x;

    for (int i = t; i < F * 4 * P; i += 256) wp1[i] = w_prep[i];
    for (int i = t; i < F * 5 * P; i += 256) wp2[i] = w_prep2[i];
    for (int i = t; i < F * P;     i += 256) bp[i]  = bias_prep[i];
    for (int i = t; i < F * F;     i += 256) adj_s[(i >> 6) * 65 + (i & 63)] = adj[i];
    __syncthreads();

    const int fq   = t >> 2;      // 0..63 feature for quad reductions
    const int part = t & 3;
    const float b2 = gb2[0];

    const int n0 = blockIdx.x * PREP_ROWS;
    for (int r = 0; r < PREP_ROWS; r++) {
        const int n = n0 + r;
        if (t < F) {
            const int f = t;
            float x    = X_obs[n * F + f];
            float mean = p_obs[n * (2 * F) + f];
            float lv   = p_obs[n * (2 * F) + F + f];
            float m    = M_obs[n * F + f];
            float err  = (x - mean) * __expf(-0.5f * lv);
            xs[f] = x; means[f] = mean; lvs[f] = lv; errs[f] = err; ms[f] = m;
            losses_out[n * F + f] = 0.5f * ((err * err + lv + TWO_LOG_LIK_C) * m);
        }
        __syncthreads();

        // ---- GCN pass 1: ax[f] = sum_g adj[f,g]*x[g]  (quad per feature) ----
        {
            const float* ar = adj_s + fq * 65;
            float a = 0.0f;
            #pragma unroll
            for (int g = part; g < F; g += 4) a = fmaf(ar[g], xs[g], a);
            a += __shfl_down_sync(0xFFFFFFFFu, a, 2, 4);
            a += __shfl_down_sync(0xFFFFFFFFu, a, 1, 4);
            if (part == 0) axs[fq] = a;
        }
        __syncthreads();
        // ---- pointwise MLP: s[g] = sum_c w2[c]*relu(ax[g]*w1[c]+b1[c]) ----
        if (t < F) {
            float a = axs[t];
            float s = 0.0f;
            #pragma unroll
            for (int c = 0; c < 32; c++) {
                float v = fmaf(a, gw1[c], gb1[c]);
                s = fmaf(gw2[c], fmaxf(v, 0.0f), s);
            }
            ss[t] = s;
        }
        __syncthreads();
        // ---- GCN pass 2: hob[f] = sum_g adj[f,g]*s[g] + b2 ----
        {
            const float* ar = adj_s + fq * 65;
            float a = 0.0f;
            #pragma unroll
            for (int g = part; g < F; g += 4) a = fmaf(ar[g], ss[g], a);
            a += __shfl_down_sync(0xFFFFFFFFu, a, 2, 4);
            a += __shfl_down_sync(0xFFFFFFFFu, a, 1, 4);
            if (part == 0) hob[fq] = a + b2;
        }
        __syncthreads();

        // ---- prep features ----
        #pragma unroll
        for (int rep = 0; rep < 4; rep++) {
            const int i = t + rep * 256;
            const int f = i >> 4, p = i & 15;
            const float* w1 = wp1 + f * (4 * P);
            float v1 = bp[f * P + p];
            v1 = fmaf(xs[f],    w1[p],          v1);
            v1 = fmaf(means[f], w1[P + p],      v1);
            v1 = fmaf(lvs[f],   w1[2 * P + p],  v1);
            v1 = fmaf(errs[f],  w1[3 * P + p],  v1);
            g_X1[(size_t)n * XK + i] = __float2half(fmaxf(v1, 0.0f) * ms[f]);

            const float* w2 = wp2 + f * (5 * P);
            float v2 = bp[f * P + p];
            v2 = fmaf(xs[f],    w2[p],          v2);
            v2 = fmaf(hob[f],   w2[P + p],      v2);
            v2 = fmaf(means[f], w2[2 * P + p],  v2);
            v2 = fmaf(lvs[f],   w2[3 * P + p],  v2);
            v2 = fmaf(errs[f],  w2[4 * P + p],  v2);
            g_X2[(size_t)n * XK + i] = __float2half(fmaxf(v2, 0.0f) * ms[f]);
        }
        __syncthreads();
    }
}

// ---------------- fp32 -> fp16 convert and gather ----------------
__global__ void __launch_bounds__(256) convert_kernel(
    const float* __restrict__ src, __half* __restrict__ dst, int n)
{
    int i = blockIdx.x * 256 + threadIdx.x;
    if (i < n) dst[i] = __float2half(src[i]);
}

__global__ void __launch_bounds__(256) gather_kernel(
    const float* __restrict__ h, const int* __restrict__ i_obs,
    __half* __restrict__ dst)
{
    int n = blockIdx.x, t = threadIdx.x;
    int idx = i_obs[n];
    dst[(size_t)n * H + t] = __float2half(h[(size_t)idx * H + t]);
}

// ---------------- Kernel 2: HMMA fp16 GEMM, 5-stage cp.async ring, fp16 out ----------------
#define BM 128
#define BN 128
#define BKB 32
#define PITCH 80
#define STAGE_MAT (BM * PITCH)
#define STAGE_BYTES (2 * STAGE_MAT)     // A, B = 20480
#define NSTAGE 5
#define GEMM_SMEM (NSTAGE * STAGE_BYTES)  // 102400

__device__ __forceinline__ void cp16(uint32_t dst, const void* src, bool pred) {
    asm volatile("cp.async.cg.shared.global [%0], [%1], 16, %2;"
                 :: "r"(dst), "l"(src), "r"(pred ? 16 : 0));
}
__device__ __forceinline__ void ldm_x4(uint32_t* r, uint32_t addr) {
    asm volatile("ldmatrix.sync.aligned.m8n8.x4.shared.b16 {%0,%1,%2,%3}, [%4];"
                 : "=r"(r[0]), "=r"(r[1]), "=r"(r[2]), "=r"(r[3]) : "r"(addr));
}
__device__ __forceinline__ void mma16816(float* c, const uint32_t* a, uint32_t b0, uint32_t b1) {
    asm volatile("mma.sync.aligned.m16n8k16.row.col.f32.f16.f16.f32 "
                 "{%0,%1,%2,%3}, {%4,%5,%6,%7}, {%8,%9}, {%0,%1,%2,%3};"
                 : "+f"(c[0]), "+f"(c[1]), "+f"(c[2]), "+f"(c[3])
                 : "r"(a[0]), "r"(a[1]), "r"(a[2]), "r"(a[3]), "r"(b0), "r"(b1));
}

__global__ void __launch_bounds__(256, 1) mma_gemm(
    const __half* __restrict__ A, const __half* __restrict__ B,
    const float* __restrict__ bias, __half* __restrict__ C,
    int M, int K, int ldc)
{
    extern __shared__ char smem_raw[];
    const uint32_t su = smem_u32(smem_raw);

    const int t    = threadIdx.x;
    const int wid  = t >> 5;
    const int lane = t & 31;
    const int bm   = blockIdx.y * BM;
    const int bn   = blockIdx.x * BN;
    const int nk   = K / BKB;

    const int wm = (wid & 1) * 64;
    const int wn = (wid >> 1) * 32;

    const int rowt  = t >> 2;
    const int chunk = t & 3;

    const int garow0 = bm + rowt, garow1 = bm + rowt + 64;
    const bool p0 = garow0 < M, p1 = garow1 < M;
    const __half* A0 = A + (size_t)(p0 ? garow0 : 0) * K + chunk * 8;
    const __half* A1 = A + (size_t)(p1 ? garow1 : 0) * K + chunk * 8;
    const __half* B0 = B + (size_t)(bn + rowt) * K + chunk * 8;
    const __half* B1 = B + (size_t)(bn + rowt + 64) * K + chunk * 8;

    const uint32_t d0 = (uint32_t)rowt * PITCH + (uint32_t)chunk * 16;
    const uint32_t d1 = d0 + 64 * PITCH;

    auto load_stage = [&](int kb, int buf) {
        const uint32_t base = su + buf * STAGE_BYTES;
        const int ke = kb * BKB;
        cp16(base + d0,             A0 + ke, p0);
        cp16(base + d1,             A1 + ke, p1);
        cp16(base + STAGE_MAT + d0, B0 + ke, true);
        cp16(base + STAGE_MAT + d1, B1 + ke, true);
        asm volatile("cp.async.commit_group;");
    };

    float acc[4][4][4];
    #pragma unroll
    for (int i = 0; i < 4; i++)
        #pragma unroll
        for (int j = 0; j < 4; j++)
            #pragma unroll
            for (int k = 0; k < 4; k++) acc[i][j][k] = 0.0f;

    load_stage(0, 0);
    load_stage(1, 1);
    load_stage(2, 2);
    load_stage(3, 3);

    int buf = 0;
    for (int kb = 0; kb < nk; kb++) {
        asm volatile("cp.async.wait_group 3;");
        __syncthreads();

        const uint32_t sa = su + buf * STAGE_BYTES;
        const uint32_t sb = sa + STAGE_MAT;

        if (kb + 4 < nk) {
            int lbuf = buf + 4; if (lbuf >= NSTAGE) lbuf -= NSTAGE;
            load_stage(kb + 4, lbuf);
        }

        #pragma unroll
        for (int ks = 0; ks < 2; ks++) {
            const uint32_t kbyte = (uint32_t)ks * 32;
            uint32_t a_r[4][4];
            const uint32_t arow = (uint32_t)(wm + (lane & 15)) * PITCH
                                + kbyte + ((uint32_t)(lane >> 4) << 4);
            #pragma unroll
            for (int mf = 0; mf < 4; mf++)
                ldm_x4(a_r[mf], sa + arow + (uint32_t)mf * 16 * PITCH);

            uint32_t b_r[2][4];
            const uint32_t brow = (uint32_t)(wn + (((lane >> 3) & 2) << 2) + (lane & 7)) * PITCH
                                + kbyte + (((uint32_t)(lane >> 3) & 1) << 4);
            #pragma unroll
            for (int nfp = 0; nfp < 2; nfp++)
                ldm_x4(b_r[nfp], sb + brow + (uint32_t)nfp * 16 * PITCH);

            #pragma unroll
            for (int mf = 0; mf < 4; mf++)
                #pragma unroll
                for (int nf = 0; nf < 4; nf++) {
                    const int nfp = nf >> 1, sub = (nf & 1) * 2;
                    mma16816(acc[mf][nf], a_r[mf], b_r[nfp][sub], b_r[nfp][sub + 1]);
                }
        }
        buf = buf + 1; if (buf >= NSTAGE) buf -= NSTAGE;
    }

    #pragma unroll
    for (int mf = 0; mf < 4; mf++) {
        const int r0 = bm + wm + mf * 16 + (lane >> 2);
        #pragma unroll
        for (int nf = 0; nf < 4; nf++) {
            const int col = bn + wn + nf * 8 + (lane & 3) * 2;
            const float b0 = bias[col], b1 = bias[col + 1];
            if (r0 < M)
                *(__half2*)(C + (size_t)r0 * ldc + col) =
                    __floats2half2_rn(acc[mf][nf][0] + b0, acc[mf][nf][1] + b1);
            if (r0 + 8 < M)
                *(__half2*)(C + (size_t)(r0 + 8) * ldc + col) =
                    __floats2half2_rn(acc[mf][nf][2] + b0, acc[mf][nf][3] + b1);
        }
    }
}

// ---------------- Kernel 3: GRU gates + MLP head (weights cached in smem) ----------------
#define GR 16
#define W1_OFF 0
#define W3_OFF (W1_OFF + 32 * 512)
#define W2_OFF (W3_OFF + 256 * 33)
#define ZIN_OFF (W2_OFF + 32 * 33)
#define Z1_OFF  (ZIN_OFF + 512)
#define Z2_OFF  (Z1_OFF + 32)
#define GATES_SMEM ((Z2_OFF + 32) * 4)

__global__ void __launch_bounds__(256) gates_mlp_kernel(
    const float* __restrict__ h, const int* __restrict__ i_obs,
    const float* __restrict__ m_w1, const float* __restrict__ m_b1,
    const float* __restrict__ m_w2, const float* __restrict__ m_b2,
    const float* __restrict__ m_w3, const float* __restrict__ m_b3,
    float* __restrict__ out_h)
{
    extern __shared__ float sm[];
    float* w1s = sm + W1_OFF;
    float* w3s = sm + W3_OFF;
    float* w2s = sm + W2_OFF;
    float* zin = sm + ZIN_OFF;
    float* z1  = sm + Z1_OFF;
    float* z2  = sm + Z2_OFF;

    const int t    = threadIdx.x;
    const int wid  = t >> 5;
    const int lane = t & 31;

    for (int i = t; i < 32 * 512; i += 256) w1s[i] = m_w1[i];
    for (int i = t; i < 256 * 32; i += 256) w3s[(i >> 5) * 33 + (i & 31)] = m_w3[i];
    for (int i = t; i < 32 * 32;  i += 256) w2s[(i >> 5) * 33 + (i & 31)] = m_w2[i];
    __syncthreads();

    const int n0 = blockIdx.x * GR;
    for (int r = 0; r < GR; r++) {
        const int n = n0 + r;
        const int idx = i_obs[n];
        const size_t b  = (size_t)n * G3;
        const size_t bh = (size_t)n * G6;

        const float hg = h[(size_t)idx * H + t];
        {
            float gi0 = __half2float(g_GI1[b + t]);
            float gi1 = __half2float(g_GI1[b + H + t]);
            float gi2 = __half2float(g_GI1[b + 2 * H + t]);
            float gh0 = __half2float(g_GH12[bh + t]);
            float gh1 = __half2float(g_GH12[bh + H + t]);
            float gh2 = __half2float(g_GH12[bh + 2 * H + t]);
            float rr = sigmoidf_(gi0 + gh0);
            float zz = sigmoidf_(gi1 + gh1);
            float ng = tanhf(gi2 + rr * gh2);
            zin[t] = (1.0f - zz) * ng + zz * hg;
        }
        {
            float gi0 = __half2float(g_GI2[b + t]);
            float gi1 = __half2float(g_GI2[b + H + t]);
            float gi2 = __half2float(g_GI2[b + 2 * H + t]);
            float gh0 = __half2float(g_GH12[bh + G3 + t]);
            float gh1 = __half2float(g_GH12[bh + G3 + H + t]);
            float gh2 = __half2float(g_GH12[bh + G3 + 2 * H + t]);
            float rr = sigmoidf_(gi0 + gh0);
            float zz = sigmoidf_(gi1 + gh1);
            float ng = tanhf(gi2 + rr * gh2);
            zin[H + t] = (1.0f - zz) * ng + zz * hg;
        }
        __syncthreads();

        #pragma unroll
        for (int q = 0; q < 4; q++) {
            const int o = 4 * wid + q;
            const float* wrow = w1s + o * 512;
            float s = 0.0f;
            #pragma unroll
            for (int j = 0; j < 16; j++)
                s = fmaf(zin[lane + 32 * j], wrow[lane + 32 * j], s);
            #pragma unroll
            for (int off = 16; off > 0; off >>= 1)
                s += __shfl_xor_sync(0xFFFFFFFFu, s, off);
            if (lane == 0) z1[o] = fmaxf(s + m_b1[o], 0.0f);
        }
        __syncthreads();

        if (t < 32) {
            const float* w = w2s + t * 33;
            float s = m_b2[t];
            #pragma unroll
            for (int k = 0; k < 32; k++) s = fmaf(z1[k], w[k], s);
            z2[t] = fmaxf(s, 0.0f);
        }
        __syncthreads();

        {
            const float* w = w3s + t * 33;
            float s = m_b3[t];
            #pragma unroll
            for (int k = 0; k < 32; k++) s = fmaf(z2[k], w[k], s);
            out_h[(size_t)idx * H + t] = s * sigmoidf_(s);
        }
        __syncthreads();
    }
}

// ---------------- launch ----------------
extern "C" void kernel_launch(void* const* d_in, const int* in_sizes, int n_in,
                              void* d_out, int out_size)
{
    const float* h         = (const float*)d_in[0];
    const float* p_obs     = (const float*)d_in[1];
    const float* X_obs     = (const float*)d_in[2];
    const float* M_obs     = (const float*)d_in[3];
    const float* adj       = (const float*)d_in[4];
    const int*   i_obs     = (const int*)  d_in[5];
    const float* w_prep    = (const float*)d_in[6];
    const float* w_prep2   = (const float*)d_in[7];
    const float* bias_prep = (const float*)d_in[8];
    const float* g1_w_ih   = (const float*)d_in[9];
    const float* g1_w_hh   = (const float*)d_in[10];
    const float* g1_b_ih   = (const float*)d_in[11];
    const float* g1_b_hh   = (const float*)d_in[12];
    const float* g2_w_ih   = (const float*)d_in[13];
    const float* g2_w_hh   = (const float*)d_in[14];
    const float* g2_b_ih   = (const float*)d_in[15];
    const float* g2_b_hh   = (const float*)d_in[16];
    const float* gcn_w1    = (const float*)d_in[17];
    const float* gcn_b1    = (const float*)d_in[18];
    const float* gcn_w2    = (const float*)d_in[19];
    const float* gcn_b2    = (const float*)d_in[20];
    const float* m_w1      = (const float*)d_in[21];
    const float* m_b1      = (const float*)d_in[22];
    const float* m_w2      = (const float*)d_in[23];
    const float* m_b2      = (const float*)d_in[24];
    const float* m_w3      = (const float*)d_in[25];
    const float* m_b3      = (const float*)d_in[26];

    float* out_h      = (float*)d_out;                           // [100000,256]
    float* out_losses = (float*)d_out + (size_t)N_TOTAL * H;     // [50000,64]

    cudaMemcpyAsync(out_h, h, (size_t)N_TOTAL * H * sizeof(float),
                    cudaMemcpyDeviceToDevice, 0);

    __half *pX1, *pX2, *pHg, *pW1ih, *pW2ih, *pWhh, *pGI1, *pGI2, *pGH12;
    float *pbhh;
    cudaGetSymbolAddress((void**)&pX1, g_X1);
    cudaGetSymbolAddress((void**)&pX2, g_X2);
    cudaGetSymbolAddress((void**)&pHg, g_Hg);
    cudaGetSymbolAddress((void**)&pW1ih, g_W1ih);
    cudaGetSymbolAddress((void**)&pW2ih, g_W2ih);
    cudaGetSymbolAddress((void**)&pWhh, g_Whh);
    cudaGetSymbolAddress((void**)&pGI1, g_GI1);
    cudaGetSymbolAddress((void**)&pGI2, g_GI2);
    cudaGetSymbolAddress((void**)&pGH12, g_GH12);
    cudaGetSymbolAddress((void**)&pbhh, g_bhh);

    // fused hh bias
    cudaMemcpyAsync(pbhh,      g1_b_hh, G3 * sizeof(float), cudaMemcpyDeviceToDevice, 0);
    cudaMemcpyAsync(pbhh + G3, g2_b_hh, G3 * sizeof(float), cudaMemcpyDeviceToDevice, 0);

    // launches 1-5: converts + gather (mma_hh deps), making launch 6 the GEMM (ncu -s 5)
    convert_kernel<<<(G3 * XK + 255) / 256, 256>>>(g1_w_ih, pW1ih, G3 * XK);
    convert_kernel<<<(G3 * XK + 255) / 256, 256>>>(g2_w_ih, pW2ih, G3 * XK);
    convert_kernel<<<(G3 * H + 255) / 256, 256>>>(g1_w_hh, pWhh, G3 * H);
    convert_kernel<<<(G3 * H + 255) / 256, 256>>>(g2_w_hh, pWhh + (size_t)G3 * H, G3 * H);
    gather_kernel<<<N_OBS, 256>>>(h, i_obs, pHg);

    cudaFuncSetAttribute(mma_gemm, cudaFuncAttributeMaxDynamicSharedMemorySize, GEMM_SMEM);

    dim3 gg_ih(G3 / 128, (N_OBS + 127) / 128);
    dim3 gg_hh(G6 / 128, (N_OBS + 127) / 128);
    // launch 6: profiled by ncu -s 5 -c 1
    mma_gemm<<<gg_hh, 256, GEMM_SMEM>>>(pHg, pWhh, pbhh, pGH12, N_OBS, H, G6);

    cudaFuncSetAttribute(prep_kernel, cudaFuncAttributeMaxDynamicSharedMemorySize, PREP_SMEM);
    prep_kernel<<<N_OBS / PREP_ROWS, 256, PREP_SMEM>>>(
        p_obs, X_obs, M_obs, adj, w_prep, w_prep2, bias_prep,
        gcn_w1, gcn_b1, gcn_w2, gcn_b2, out_losses);

    mma_gemm<<<gg_ih, 256, GEMM_SMEM>>>(pX1, pW1ih, g1_b_ih, pGI1, N_OBS, XK, G3);
    mma_gemm<<<gg_ih, 256, GEMM_SMEM>>>(pX2, pW2ih, g2_b_ih, pGI2, N_OBS, XK, G3);

    cudaFuncSetAttribute(gates_mlp_kernel, cudaFuncAttributeMaxDynamicSharedMemorySize, GATES_SMEM);
    gates_mlp_kernel<<<N_OBS / GR, 256, GATES_SMEM>>>(h, i_obs, m_w1, m_b1, m_w2, m_b2,
                                                      m_w3, m_b3, out_h);
}